// round 7
// baseline (speedup 1.0000x reference)
#include <cuda_runtime.h>
#include <cuda_fp16.h>
#include <cstdint>

#define B_   2
#define T_   2048
#define D_   768
#define H_   12
#define DH_  64
#define M_   (B_ * T_)   // 4096

// ---------------- scratch (static device globals; no allocation) ----------------
__device__ half  g_Xh [M_ * D_];             // X in fp16
__device__ half  g_Wqh[D_ * D_];
__device__ half  g_Wkh[D_ * D_];
__device__ half  g_Wvh[D_ * D_];
__device__ half  g_Woh[D_ * D_];
__device__ half  g_Qh [B_ * H_ * T_ * DH_];  // [B,H,T,Dh] fp16
__device__ half  g_Kh [B_ * H_ * T_ * DH_];
__device__ half  g_Vh [B_ * H_ * T_ * DH_];
__device__ float g_VS [B_ * H_ * T_ * DH_];  // suffix sums of V (fp32)
__device__ half  g_AOh[M_ * D_];             // attention out, [B,T, H*Dh] fp16
__device__ float g_CT [24 * 64 * DH_];       // per-chunk V totals

// ---------------- helpers ----------------
#define MMA_F16(c, a, b)                                                         \
    asm volatile(                                                                \
        "mma.sync.aligned.m16n8k16.row.col.f32.f16.f16.f32 "                     \
        "{%0,%1,%2,%3},{%4,%5,%6,%7},{%8,%9},{%0,%1,%2,%3};"                     \
        : "+f"((c)[0]), "+f"((c)[1]), "+f"((c)[2]), "+f"((c)[3])                 \
        : "r"((a)[0]), "r"((a)[1]), "r"((a)[2]), "r"((a)[3]),                    \
          "r"((b)[0]), "r"((b)[1]))

__device__ __forceinline__ void ldmx4(uint32_t* r, uint32_t addr) {
    asm volatile("ldmatrix.sync.aligned.m8n8.x4.shared.b16 {%0,%1,%2,%3}, [%4];"
                 : "=r"(r[0]), "=r"(r[1]), "=r"(r[2]), "=r"(r[3]) : "r"(addr));
}
__device__ __forceinline__ void ldmx4t(uint32_t* r, uint32_t addr) {
    asm volatile("ldmatrix.sync.aligned.m8n8.x4.trans.shared.b16 {%0,%1,%2,%3}, [%4];"
                 : "=r"(r[0]), "=r"(r[1]), "=r"(r[2]), "=r"(r[3]) : "r"(addr));
}
__device__ __forceinline__ uint32_t h2u(half2 h) { return *reinterpret_cast<uint32_t*>(&h); }

__device__ __forceinline__ void cpa16(uint32_t saddr, const void* g) {
    asm volatile("cp.async.cg.shared.global [%0], [%1], 16;" :: "r"(saddr), "l"(g));
}
__device__ __forceinline__ void cp_commit() { asm volatile("cp.async.commit_group;"); }
template <int N>
__device__ __forceinline__ void cp_wait() { asm volatile("cp.async.wait_group %0;" :: "n"(N)); }

// ---------------- fp32 -> fp16 conversion of X and the 4 weight matrices --------
#define XTOT4 (M_ * D_ / 4)     // 786432
#define WTOT4 (D_ * D_ / 4)     // 147456

__global__ __launch_bounds__(256)
void cvt_all(const float* __restrict__ X,
             const float* __restrict__ Wq, const float* __restrict__ Wk,
             const float* __restrict__ Wv, const float* __restrict__ Wo)
{
    int i = blockIdx.x * 256 + threadIdx.x;
    const int total = XTOT4 + 4 * WTOT4;
    if (i >= total) return;
    const float* src; half* dst; int off;
    if (i < XTOT4) { src = X; dst = g_Xh; off = i; }
    else {
        int j = i - XTOT4;
        int w = j / WTOT4;
        off = j - w * WTOT4;
        src = (w == 0) ? Wq : (w == 1) ? Wk : (w == 2) ? Wv : Wo;
        dst = (w == 0) ? g_Wqh : (w == 1) ? g_Wkh : (w == 2) ? g_Wvh : g_Woh;
    }
    float4 v = ((const float4*)src)[off];
    uint2 u = make_uint2(h2u(__floats2half2_rn(v.x, v.y)),
                         h2u(__floats2half2_rn(v.z, v.w)));
    ((uint2*)dst)[off] = u;
}

// ---------------- fp16 GEMM mainloop, cp.async double-buffered ------------------
#define LDA 72
#define GA_SZ (128 * LDA)            // halves per A stage
#define GW_SZ (64 * LDA)
#define GEMM_SMEM ((2 * GA_SZ + 2 * GW_SZ) * 2)   // bytes = 55296

__device__ __forceinline__
void gemm_h_mainloop(const half* __restrict__ A, const half* __restrict__ W,
                     float c[2][4][4], half* As, half* Ws)
{
    const int tid  = threadIdx.x;
    const int lane = tid & 31;
    const int wid  = tid >> 5;
    const int wm   = wid & 3;
    const int wn   = wid >> 2;
    const int m0   = blockIdx.y * 128;
    const int n0   = blockIdx.x * 64;
    const int lrow = lane & 15;
    const int lcol = (lane >> 4) * 8;

#pragma unroll
    for (int mi = 0; mi < 2; mi++)
#pragma unroll
        for (int j = 0; j < 4; j++)
#pragma unroll
            for (int r = 0; r < 4; r++) c[mi][j][r] = 0.f;

    const uint32_t asb = (uint32_t)__cvta_generic_to_shared(As);
    const uint32_t wsb = (uint32_t)__cvta_generic_to_shared(Ws);

    // per-thread load coordinates
    const int arow[4] = { (tid + 0) >> 3, (tid + 256) >> 3, (tid + 512) >> 3, (tid + 768) >> 3 };
    const int ac8     = (tid & 7) * 8;
    const int wrow[2] = { (tid + 0) >> 3, (tid + 256) >> 3 };

    // stage 0
    {
#pragma unroll
        for (int r = 0; r < 4; r++)
            cpa16(asb + (arow[r] * LDA + ac8) * 2, A + (size_t)(m0 + arow[r]) * D_ + ac8);
#pragma unroll
        for (int r = 0; r < 2; r++)
            cpa16(wsb + (wrow[r] * LDA + ac8) * 2, W + (size_t)wrow[r] * D_ + n0 + ac8);
        cp_commit();
    }

    const uint32_t aaddr_l = (uint32_t)__cvta_generic_to_shared(
        &As[(wm * 32 + lrow) * LDA + lcol]);
    const uint32_t baddr_l = (uint32_t)__cvta_generic_to_shared(
        &Ws[lrow * LDA + wn * 32 + lcol]);

    const int NIT = D_ / 64;   // 12
    for (int it = 0; it < NIT; it++) {
        if (it + 1 < NIT) {
            const int kk = (it + 1) * 64;
            const uint32_t ao = ((it + 1) & 1) * (GA_SZ * 2);
            const uint32_t wo = ((it + 1) & 1) * (GW_SZ * 2);
#pragma unroll
            for (int r = 0; r < 4; r++)
                cpa16(asb + ao + (arow[r] * LDA + ac8) * 2,
                      A + (size_t)(m0 + arow[r]) * D_ + kk + ac8);
#pragma unroll
            for (int r = 0; r < 2; r++)
                cpa16(wsb + wo + (wrow[r] * LDA + ac8) * 2,
                      W + (size_t)(kk + wrow[r]) * D_ + n0 + ac8);
            cp_commit();
            cp_wait<1>();
        } else {
            cp_wait<0>();
        }
        __syncthreads();

        const uint32_t aaddr0 = aaddr_l + (it & 1) * (GA_SZ * 2);
        const uint32_t aaddr1 = aaddr0 + 16 * LDA * 2;
        const uint32_t baddr  = baddr_l + (it & 1) * (GW_SZ * 2);

#pragma unroll
        for (int ks = 0; ks < 4; ks++) {
            uint32_t af[2][4];
            ldmx4(af[0], aaddr0 + ks * 32);
            ldmx4(af[1], aaddr1 + ks * 32);
#pragma unroll
            for (int ni = 0; ni < 2; ni++) {
                uint32_t bf[4];
                ldmx4t(bf, baddr + (ks * 16 * LDA + ni * 16) * 2);
                uint32_t b0[2] = { bf[0], bf[1] };
                uint32_t b1[2] = { bf[2], bf[3] };
                MMA_F16(c[0][ni * 2],     af[0], b0);
                MMA_F16(c[0][ni * 2 + 1], af[0], b1);
                MMA_F16(c[1][ni * 2],     af[1], b0);
                MMA_F16(c[1][ni * 2 + 1], af[1], b1);
            }
        }
        __syncthreads();
    }
}

// QKV projection: blockIdx.z selects matrix; epilogue scatters half into [B,H,T,Dh].
__global__ __launch_bounds__(256, 2)
void gemm_qkv_h(const float* __restrict__ bq, const float* __restrict__ bk,
                const float* __restrict__ bv)
{
    extern __shared__ __align__(16) half gsm[];
    half* As = gsm;
    half* Ws = gsm + 2 * GA_SZ;

    const int z = blockIdx.z;
    const half*  W  = (z == 0) ? g_Wqh : (z == 1) ? g_Wkh : g_Wvh;
    const float* bb = (z == 0) ? bq    : (z == 1) ? bk    : bv;
    half*        Cd = (z == 0) ? g_Qh  : (z == 1) ? g_Kh  : g_Vh;

    float c[2][4][4];
    gemm_h_mainloop(g_Xh, W, c, As, Ws);

    const int lane = threadIdx.x & 31;
    const int wid  = threadIdx.x >> 5;
    const int wm   = wid & 3;
    const int wn   = wid >> 2;
    const int gr   = lane >> 2;
    const int gc   = lane & 3;
    const int m0   = blockIdx.y * 128;
    const int n0   = blockIdx.x * 64;

#pragma unroll
    for (int mi = 0; mi < 2; mi++) {
#pragma unroll
        for (int j = 0; j < 4; j++) {
            int col = n0 + wn * 32 + j * 8 + 2 * gc;
            float b0 = bb[col], b1 = bb[col + 1];
            int h  = col >> 6;
            int dh = col & 63;
#pragma unroll
            for (int hp = 0; hp < 2; hp++) {
                int row = m0 + wm * 32 + mi * 16 + gr + hp * 8;
                int bt  = row >> 11;
                int t   = row & (T_ - 1);
                half2 v = __floats2half2_rn(c[mi][j][hp * 2] + b0,
                                            c[mi][j][hp * 2 + 1] + b1);
                *(half2*)&Cd[((size_t)(bt * H_ + h) * T_ + t) * DH_ + dh] = v;
            }
        }
    }
}

// Output projection: AO(half) @ Wo + bo -> fp32 out.
__global__ __launch_bounds__(256, 2)
void gemm_out_h(const float* __restrict__ bo, float* __restrict__ out)
{
    extern __shared__ __align__(16) half gsm[];
    half* As = gsm;
    half* Ws = gsm + 2 * GA_SZ;

    float c[2][4][4];
    gemm_h_mainloop(g_AOh, g_Woh, c, As, Ws);

    const int lane = threadIdx.x & 31;
    const int wid  = threadIdx.x >> 5;
    const int wm   = wid & 3;
    const int wn   = wid >> 2;
    const int gr   = lane >> 2;
    const int gc   = lane & 3;
    const int m0   = blockIdx.y * 128;
    const int n0   = blockIdx.x * 64;

#pragma unroll
    for (int mi = 0; mi < 2; mi++) {
#pragma unroll
        for (int j = 0; j < 4; j++) {
            int col = n0 + wn * 32 + j * 8 + 2 * gc;
            float b0 = bo[col], b1 = bo[col + 1];
#pragma unroll
            for (int hp = 0; hp < 2; hp++) {
                int row = m0 + wm * 32 + mi * 16 + gr + hp * 8;
                *(float2*)&out[(size_t)row * D_ + col] =
                    make_float2(c[mi][j][hp * 2] + b0, c[mi][j][hp * 2 + 1] + b1);
            }
        }
    }
}

// ---------------- V suffix sums per (b,h): VS[t] = sum_{j>t} V[j] ----------------
__global__ __launch_bounds__(64)
void vsuffix_a()
{
    const int bh = blockIdx.y;
    const int ch = blockIdx.x;                 // 0..63, 32 rows each
    const int d  = threadIdx.x;
    const half* V = g_Vh + (size_t)bh * T_ * DH_;
    float*      S = g_VS + (size_t)bh * T_ * DH_;
    const int t0 = ch * 32;
    float sum = 0.f;
#pragma unroll 8
    for (int t = t0 + 31; t >= t0; t--) {
        S[(size_t)t * DH_ + d] = sum;
        sum += __half2float(V[(size_t)t * DH_ + d]);
    }
    g_CT[((size_t)bh * 64 + ch) * DH_ + d] = sum;
}

__global__ __launch_bounds__(64)
void vsuffix_b()
{
    const int bh = blockIdx.y;
    const int ch = blockIdx.x;
    const int d  = threadIdx.x;
    if (ch == 63) return;
    float off = 0.f;
#pragma unroll 8
    for (int cc = ch + 1; cc < 64; cc++)
        off += g_CT[((size_t)bh * 64 + cc) * DH_ + d];
    float* S = g_VS + (size_t)bh * T_ * DH_;
    const int t0 = ch * 32;
#pragma unroll 8
    for (int t = t0; t < t0 + 32; t++)
        S[(size_t)t * DH_ + d] += off;
}

// ---------------- fp16 TC causal attention: 128-row Q tiles, cp.async DB --------
// 8 warps, each owns 16 q-rows x all 64 keys. No cross-warp reduction.
#define LDH 72
#define KV_SZ (64 * LDH)                       // halves per K or V stage
#define ATT_SMEM ((128 * LDH + 4 * KV_SZ) * 2) // bytes = 55296

__global__ __launch_bounds__(256, 2)
void attn_tc()
{
    extern __shared__ __align__(16) half asm_[];
    half* Qh = asm_;                 // 128 x LDH
    half* Kh = Qh + 128 * LDH;       // 2 stages
    half* Vh = Kh + 2 * KV_SZ;       // 2 stages

    const int tid  = threadIdx.x;
    const int lane = tid & 31;
    const int wid  = tid >> 5;            // 0..7: rows wid*16..+15
    const int gr   = lane >> 2;
    const int gc   = lane & 3;
    const int lrow = lane & 15;
    const int lcol = (lane >> 4) * 8;

    const int bh  = blockIdx.y;
    const int qt  = gridDim.x - 1 - blockIdx.x;   // heavy tiles first
    const int q0  = qt * 128;
    const int nkt = 2 * qt + 2;

    const half*  Qg   = g_Qh + (size_t)bh * T_ * DH_;
    const half*  Kg   = g_Kh + (size_t)bh * T_ * DH_;
    const half*  Vg   = g_Vh + (size_t)bh * T_ * DH_;
    const float* Vsuf = g_VS + (size_t)bh * T_ * DH_;

    const uint32_t qsb = (uint32_t)__cvta_generic_to_shared(Qh);
    const uint32_t ksb = (uint32_t)__cvta_generic_to_shared(Kh);
    const uint32_t vsb = (uint32_t)__cvta_generic_to_shared(Vh);

    // ---- group 0: Q tile (128x64) + K/V stage 0 ----
    {
        const int c8 = (tid & 7) * 8;
#pragma unroll
        for (int rr = 0; rr < 4; rr++) {
            int row = (tid + rr * 256) >> 3;      // 0..127
            cpa16(qsb + (row * LDH + c8) * 2, Qg + (size_t)(q0 + row) * DH_ + c8);
        }
#pragma unroll
        for (int rr = 0; rr < 2; rr++) {
            int row = (tid + rr * 256) >> 3;      // 0..63
            const size_t goff = (size_t)row * DH_ + c8;
            cpa16(ksb + (row * LDH + c8) * 2, Kg + goff);
            cpa16(vsb + (row * LDH + c8) * 2, Vg + goff);
        }
        cp_commit();
    }

    float o[8][4];
#pragma unroll
    for (int ni = 0; ni < 8; ni++)
#pragma unroll
        for (int r = 0; r < 4; r++) o[ni][r] = 0.f;
    float rsum0 = 0.f, rsum1 = 0.f;
    uint32_t qf[4][4];

    const uint32_t kaddr_l = (uint32_t)__cvta_generic_to_shared(&Kh[lrow * LDH + lcol]);
    const uint32_t vaddr_l = (uint32_t)__cvta_generic_to_shared(&Vh[lrow * LDH + lcol]);

    for (int kt = 0; kt < nkt; kt++) {
        if (kt + 1 < nkt) {
            const int c8 = (tid & 7) * 8;
            const uint32_t so = ((kt + 1) & 1) * (KV_SZ * 2);
#pragma unroll
            for (int rr = 0; rr < 2; rr++) {
                int row = (tid + rr * 256) >> 3;
                const size_t goff = (size_t)((kt + 1) * 64 + row) * DH_ + c8;
                cpa16(ksb + so + (row * LDH + c8) * 2, Kg + goff);
                cpa16(vsb + so + (row * LDH + c8) * 2, Vg + goff);
            }
            cp_commit();
            cp_wait<1>();
        } else {
            cp_wait<0>();
        }
        __syncthreads();

        if (kt == 0) {
            uint32_t qaddr = qsb + ((wid * 16 + lrow) * LDH + lcol) * 2;
#pragma unroll
            for (int ks = 0; ks < 4; ks++)
                ldmx4(qf[ks], qaddr + ks * 32);
        }

        const bool lastT   = (kt == nkt - 1);
        const bool skipAll = lastT && (wid < 4);

        if (!skipAll) {
            const uint32_t kaddr = kaddr_l + (kt & 1) * (KV_SZ * 2);
            const uint32_t vaddr = vaddr_l + (kt & 1) * (KV_SZ * 2);

            // ---- S = Q . K^T (16 rows x 64 keys) ----
            float s[8][4];
#pragma unroll
            for (int j = 0; j < 8; j++)
#pragma unroll
                for (int r = 0; r < 4; r++) s[j][r] = 0.f;

#pragma unroll
            for (int ks = 0; ks < 4; ks++) {
#pragma unroll
                for (int kg = 0; kg < 4; kg++) {
                    uint32_t rk[4];
                    ldmx4(rk, kaddr + kg * 16 * LDH * 2 + ks * 32);
                    uint32_t b0[2] = { rk[0], rk[2] };
                    uint32_t b1[2] = { rk[1], rk[3] };
                    MMA_F16(s[kg * 2],     qf[ks], b0);
                    MMA_F16(s[kg * 2 + 1], qf[ks], b1);
                }
            }

            // ---- exp + mask + rowsum; pack P ----
            const bool needMask = (kt >= nkt - 2) &&
                                  ((kt == nkt - 2) ? (wid < 4) : true);
            const int row0 = q0 + wid * 16 + gr;
            uint32_t pl[8], ph[8];
#pragma unroll
            for (int j = 0; j < 8; j++) {
                float p0 = __expf(s[j][0] * 0.125f);
                float p1 = __expf(s[j][1] * 0.125f);
                float p2 = __expf(s[j][2] * 0.125f);
                float p3 = __expf(s[j][3] * 0.125f);
                if (needMask) {
                    int colg = kt * 64 + j * 8 + 2 * gc;
                    if (colg     > row0)     p0 = 0.f;
                    if (colg + 1 > row0)     p1 = 0.f;
                    if (colg     > row0 + 8) p2 = 0.f;
                    if (colg + 1 > row0 + 8) p3 = 0.f;
                }
                rsum0 += p0 + p1;
                rsum1 += p2 + p3;
                pl[j] = h2u(__floats2half2_rn(p0, p1));
                ph[j] = h2u(__floats2half2_rn(p2, p3));
            }

            // ---- O += P . V ----
#pragma unroll
            for (int ks = 0; ks < 4; ks++) {
                uint32_t a[4] = { pl[ks * 2], ph[ks * 2], pl[ks * 2 + 1], ph[ks * 2 + 1] };
                uint32_t vb = vaddr + ks * 16 * LDH * 2;
#pragma unroll
                for (int dg = 0; dg < 4; dg++) {
                    uint32_t rv[4];
                    ldmx4t(rv, vb + dg * 32);
                    uint32_t bA[2] = { rv[0], rv[1] };
                    uint32_t bB[2] = { rv[2], rv[3] };
                    MMA_F16(o[dg * 2],     a, bA);
                    MMA_F16(o[dg * 2 + 1], a, bB);
                }
            }
        }
        __syncthreads();
    }

    // ---- rowsum reduce over the 4 quad lanes ----
    rsum0 += __shfl_xor_sync(0xffffffffu, rsum0, 1);
    rsum0 += __shfl_xor_sync(0xffffffffu, rsum0, 2);
    rsum1 += __shfl_xor_sync(0xffffffffu, rsum1, 1);
    rsum1 += __shfl_xor_sync(0xffffffffu, rsum1, 2);

    // ---- epilogue: each warp writes its own 16 rows ----
    const int b = bh / H_;
    const int h = bh - b * H_;
#pragma unroll
    for (int half_ = 0; half_ < 2; half_++) {
        int qi = q0 + wid * 16 + gr + 8 * half_;
        float own = (half_ == 0) ? rsum0 : rsum1;
        float denom = own + (float)(T_ - 1 - qi);
        float inv = 1.f / denom;
        half* dst = g_AOh + ((size_t)(b * T_ + qi)) * D_ + h * DH_;
        const float* vs = Vsuf + (size_t)qi * DH_;
#pragma unroll
        for (int ni = 0; ni < 8; ni++) {
            int c = ni * 8 + 2 * gc;
            float2 vsv = *(const float2*)&vs[c];
            float v0 = (o[ni][half_ * 2 + 0] + vsv.x) * inv;
            float v1 = (o[ni][half_ * 2 + 1] + vsv.y) * inv;
            *(half2*)&dst[c] = __floats2half2_rn(v0, v1);
        }
    }
}

// ---------------- launch -----------------
extern "C" void kernel_launch(void* const* d_in, const int* in_sizes, int n_in,
                              void* d_out, int out_size)
{
    const float* X  = (const float*)d_in[0];
    const float* Wq = (const float*)d_in[1];
    const float* bq = (const float*)d_in[2];
    const float* Wk = (const float*)d_in[3];
    const float* bk = (const float*)d_in[4];
    const float* Wv = (const float*)d_in[5];
    const float* bv = (const float*)d_in[6];
    const float* Wo = (const float*)d_in[7];
    const float* bo = (const float*)d_in[8];
    float* out = (float*)d_out;

    cudaFuncSetAttribute(gemm_qkv_h, cudaFuncAttributeMaxDynamicSharedMemorySize, GEMM_SMEM);
    cudaFuncSetAttribute(gemm_out_h, cudaFuncAttributeMaxDynamicSharedMemorySize, GEMM_SMEM);
    cudaFuncSetAttribute(attn_tc,    cudaFuncAttributeMaxDynamicSharedMemorySize, ATT_SMEM);

    const int total4 = XTOT4 + 4 * WTOT4;
    cvt_all<<<(total4 + 255) / 256, 256>>>(X, Wq, Wk, Wv, Wo);
    gemm_qkv_h<<<dim3(D_ / 64, M_ / 128, 3), 256, GEMM_SMEM>>>(bq, bk, bv);
    vsuffix_a<<<dim3(64, 24), 64>>>();
    vsuffix_b<<<dim3(64, 24), 64>>>();
    attn_tc<<<dim3(T_ / 128, B_ * H_), 256, ATT_SMEM>>>();
    gemm_out_h<<<dim3(D_ / 64, M_ / 128), 256, GEMM_SMEM>>>(bo, out);
}

// round 9
// speedup vs baseline: 1.0895x; 1.0895x over previous
#include <cuda_runtime.h>
#include <cuda_fp16.h>
#include <cstdint>

#define B_   2
#define T_   2048
#define D_   768
#define H_   12
#define DH_  64
#define M_   (B_ * T_)   // 4096

// ---------------- scratch (static device globals; no allocation) ----------------
__device__ half  g_Xh [M_ * D_];             // X in fp16
__device__ half  g_Wqh[D_ * D_];
__device__ half  g_Wkh[D_ * D_];
__device__ half  g_Wvh[D_ * D_];
__device__ half  g_Woh[D_ * D_];
__device__ half  g_Qh [B_ * H_ * T_ * DH_];  // [B,H,T,Dh] fp16
__device__ half  g_Kh [B_ * H_ * T_ * DH_];
__device__ half  g_Vh [B_ * H_ * T_ * DH_];
__device__ half  g_AOh[M_ * D_];             // attention out, [B,T, H*Dh] fp16
__device__ float g_TT [24 * 32 * DH_];       // per-(bh,tile) V totals
__device__ float g_TS [24 * 33 * DH_];       // per-(bh,tile) V tile-suffix sums

// ---------------- helpers ----------------
#define MMA_F16(c, a, b)                                                         \
    asm volatile(                                                                \
        "mma.sync.aligned.m16n8k16.row.col.f32.f16.f16.f32 "                     \
        "{%0,%1,%2,%3},{%4,%5,%6,%7},{%8,%9},{%0,%1,%2,%3};"                     \
        : "+f"((c)[0]), "+f"((c)[1]), "+f"((c)[2]), "+f"((c)[3])                 \
        : "r"((a)[0]), "r"((a)[1]), "r"((a)[2]), "r"((a)[3]),                    \
          "r"((b)[0]), "r"((b)[1]))

__device__ __forceinline__ void ldmx4(uint32_t* r, uint32_t addr) {
    asm volatile("ldmatrix.sync.aligned.m8n8.x4.shared.b16 {%0,%1,%2,%3}, [%4];"
                 : "=r"(r[0]), "=r"(r[1]), "=r"(r[2]), "=r"(r[3]) : "r"(addr));
}
__device__ __forceinline__ void ldmx4t(uint32_t* r, uint32_t addr) {
    asm volatile("ldmatrix.sync.aligned.m8n8.x4.trans.shared.b16 {%0,%1,%2,%3}, [%4];"
                 : "=r"(r[0]), "=r"(r[1]), "=r"(r[2]), "=r"(r[3]) : "r"(addr));
}
__device__ __forceinline__ uint32_t h2u(half2 h) { return *reinterpret_cast<uint32_t*>(&h); }

// ---------------- fp32 -> fp16 conversion of X and the 4 weight matrices --------
#define XTOT4 (M_ * D_ / 4)     // 786432
#define WTOT4 (D_ * D_ / 4)     // 147456

__global__ __launch_bounds__(256)
void cvt_all(const float* __restrict__ X,
             const float* __restrict__ Wq, const float* __restrict__ Wk,
             const float* __restrict__ Wv, const float* __restrict__ Wo)
{
    int i = blockIdx.x * 256 + threadIdx.x;
    const int total = XTOT4 + 4 * WTOT4;
    if (i >= total) return;
    const float* src; half* dst; int off;
    if (i < XTOT4) { src = X; dst = g_Xh; off = i; }
    else {
        int j = i - XTOT4;
        int w = j / WTOT4;
        off = j - w * WTOT4;
        src = (w == 0) ? Wq : (w == 1) ? Wk : (w == 2) ? Wv : Wo;
        dst = (w == 0) ? g_Wqh : (w == 1) ? g_Wkh : (w == 2) ? g_Wvh : g_Woh;
    }
    float4 v = ((const float4*)src)[off];
    uint2 u = make_uint2(h2u(__floats2half2_rn(v.x, v.y)),
                         h2u(__floats2half2_rn(v.z, v.w)));
    ((uint2*)dst)[off] = u;
}

// ---------------- fp16 tensor-core GEMM mainloop (128x64 tile, k-chunk 64) ------
#define LDA 72

__device__ __forceinline__
void gemm_h_mainloop(const half* __restrict__ A, const half* __restrict__ W,
                     float c[2][4][4], half* As, half* Ws)
{
    const int tid  = threadIdx.x;
    const int lane = tid & 31;
    const int wid  = tid >> 5;
    const int wm   = wid & 3;
    const int wn   = wid >> 2;
    const int m0   = blockIdx.y * 128;
    const int n0   = blockIdx.x * 64;
    const int lrow = lane & 15;
    const int lcol = (lane >> 4) * 8;

#pragma unroll
    for (int mi = 0; mi < 2; mi++)
#pragma unroll
        for (int j = 0; j < 4; j++)
#pragma unroll
            for (int r = 0; r < 4; r++) c[mi][j][r] = 0.f;

    const uint32_t aaddr0 = (uint32_t)__cvta_generic_to_shared(
        &As[(wm * 32 + lrow) * LDA + lcol]);
    const uint32_t aaddr1 = aaddr0 + 16 * LDA * 2;
    const uint32_t baddr  = (uint32_t)__cvta_generic_to_shared(
        &Ws[lrow * LDA + wn * 32 + lcol]);

    for (int kk = 0; kk < D_; kk += 64) {
        // A tile 128x64 halves = 1024 uint4
#pragma unroll
        for (int r = 0; r < 4; r++) {
            int idx = tid + r * 256;
            int row = idx >> 3;
            int c8  = (idx & 7) * 8;
            *(uint4*)&As[row * LDA + c8] =
                *(const uint4*)(A + (size_t)(m0 + row) * D_ + kk + c8);
        }
        // W tile 64x64 halves = 512 uint4
#pragma unroll
        for (int r = 0; r < 2; r++) {
            int idx = tid + r * 256;
            int row = idx >> 3;
            int c8  = (idx & 7) * 8;
            *(uint4*)&Ws[row * LDA + c8] =
                *(const uint4*)(W + (size_t)(kk + row) * D_ + n0 + c8);
        }
        __syncthreads();

#pragma unroll
        for (int ks = 0; ks < 4; ks++) {
            uint32_t af[2][4];
            ldmx4(af[0], aaddr0 + ks * 32);
            ldmx4(af[1], aaddr1 + ks * 32);
#pragma unroll
            for (int ni = 0; ni < 2; ni++) {
                uint32_t bf[4];
                ldmx4t(bf, baddr + (ks * 16 * LDA + ni * 16) * 2);
                uint32_t b0[2] = { bf[0], bf[1] };
                uint32_t b1[2] = { bf[2], bf[3] };
                MMA_F16(c[0][ni * 2],     af[0], b0);
                MMA_F16(c[0][ni * 2 + 1], af[0], b1);
                MMA_F16(c[1][ni * 2],     af[1], b0);
                MMA_F16(c[1][ni * 2 + 1], af[1], b1);
            }
        }
        __syncthreads();
    }
}

// QKV projection: blockIdx.z selects matrix; epilogue scatters half into [B,H,T,Dh].
__global__ __launch_bounds__(256)
void gemm_qkv_h(const float* __restrict__ bq, const float* __restrict__ bk,
                const float* __restrict__ bv)
{
    __shared__ half As[128 * LDA];
    __shared__ half Ws[64 * LDA];

    const int z = blockIdx.z;
    const half*  W  = (z == 0) ? g_Wqh : (z == 1) ? g_Wkh : g_Wvh;
    const float* bb = (z == 0) ? bq    : (z == 1) ? bk    : bv;
    half*        Cd = (z == 0) ? g_Qh  : (z == 1) ? g_Kh  : g_Vh;

    float c[2][4][4];
    gemm_h_mainloop(g_Xh, W, c, As, Ws);

    const int lane = threadIdx.x & 31;
    const int wid  = threadIdx.x >> 5;
    const int wm   = wid & 3;
    const int wn   = wid >> 2;
    const int gr   = lane >> 2;
    const int gc   = lane & 3;
    const int m0   = blockIdx.y * 128;
    const int n0   = blockIdx.x * 64;

#pragma unroll
    for (int mi = 0; mi < 2; mi++) {
#pragma unroll
        for (int j = 0; j < 4; j++) {
            int col = n0 + wn * 32 + j * 8 + 2 * gc;
            float b0 = bb[col], b1 = bb[col + 1];
            int h  = col >> 6;
            int dh = col & 63;
#pragma unroll
            for (int hp = 0; hp < 2; hp++) {
                int row = m0 + wm * 32 + mi * 16 + gr + hp * 8;
                int bt  = row >> 11;
                int t   = row & (T_ - 1);
                half2 v = __floats2half2_rn(c[mi][j][hp * 2] + b0,
                                            c[mi][j][hp * 2 + 1] + b1);
                *(half2*)&Cd[((size_t)(bt * H_ + h) * T_ + t) * DH_ + dh] = v;
            }
        }
    }
}

// Output projection: AO(half) @ Wo + bo -> fp32 out.
__global__ __launch_bounds__(256)
void gemm_out_h(const float* __restrict__ bo, float* __restrict__ out)
{
    __shared__ half As[128 * LDA];
    __shared__ half Ws[64 * LDA];

    float c[2][4][4];
    gemm_h_mainloop(g_AOh, g_Woh, c, As, Ws);

    const int lane = threadIdx.x & 31;
    const int wid  = threadIdx.x >> 5;
    const int wm   = wid & 3;
    const int wn   = wid >> 2;
    const int gr   = lane >> 2;
    const int gc   = lane & 3;
    const int m0   = blockIdx.y * 128;
    const int n0   = blockIdx.x * 64;

#pragma unroll
    for (int mi = 0; mi < 2; mi++) {
#pragma unroll
        for (int j = 0; j < 4; j++) {
            int col = n0 + wn * 32 + j * 8 + 2 * gc;
            float b0 = bo[col], b1 = bo[col + 1];
#pragma unroll
            for (int hp = 0; hp < 2; hp++) {
                int row = m0 + wm * 32 + mi * 16 + gr + hp * 8;
                *(float2*)&out[(size_t)row * D_ + col] =
                    make_float2(c[mi][j][hp * 2] + b0, c[mi][j][hp * 2 + 1] + b1);
            }
        }
    }
}

// ---------------- V tile totals + tile suffixes ----------------
// TT[bh][t][d] = sum of V rows in 64-row tile t; TS[bh][t][d] = sum_{tt>=t} TT.
__global__ __launch_bounds__(64)
void tiletot()
{
    const int bh = blockIdx.y;
    const int tl = blockIdx.x;                 // 0..31
    const int d  = threadIdx.x;
    const half* V = g_Vh + (size_t)bh * T_ * DH_ + (size_t)tl * 64 * DH_ + d;
    float sum = 0.f;
#pragma unroll 16
    for (int t = 0; t < 64; t++)
        sum += __half2float(V[(size_t)t * DH_]);
    g_TT[((size_t)bh * 32 + tl) * DH_ + d] = sum;
}

__global__ __launch_bounds__(64)
void tilesuf()
{
    const int bh = blockIdx.x;
    const int d  = threadIdx.x;
    float s = 0.f;
    g_TS[((size_t)bh * 33 + 32) * DH_ + d] = 0.f;
    for (int t = 31; t >= 0; t--) {
        s += g_TT[((size_t)bh * 32 + t) * DH_ + d];
        g_TS[((size_t)bh * 33 + t) * DH_ + d] = s;
    }
}

// ---------------- fp16 tensor-core causal attention (zero-fill semantics) -------
// 8 warps = 4 (m16 q-row groups) x 2 (32-key halves). Masked diag entries get
// p=1 (exp(0)) and flow through PV natively; beyond-range tiles are corrected by
// the per-CTA tile-suffix vector TS[bh][qt+1] and count T - (qt+1)*64.
#define LDH 72

__global__ __launch_bounds__(256, 2)
void attn_tc()
{
    __shared__ __align__(16) uint8_t smraw[3 * 64 * LDH * 2 + 4 * 16 * 64 * 4 + 64 * 4];
    half* Qh = (half*)smraw;
    half* Kh = Qh + 64 * LDH;
    half* Vh = Kh + 64 * LDH;
    float* redO = (float*)(smraw + 3 * 64 * LDH * 2);
    float* redS = redO + 4 * 16 * 64;

    const int tid  = threadIdx.x;
    const int lane = tid & 31;
    const int wid  = tid >> 5;
    const int wm   = wid & 3;
    const int wh   = wid >> 2;
    const int gr   = lane >> 2;
    const int gc   = lane & 3;
    const int lrow = lane & 15;
    const int lcol = (lane >> 4) * 8;

    const int bh = blockIdx.y;
    const int qt = gridDim.x - 1 - blockIdx.x;    // heavy tiles first
    const int q0 = qt * 64;

    const half* Qg = g_Qh + (size_t)bh * T_ * DH_;
    const half* Kg = g_Kh + (size_t)bh * T_ * DH_;
    const half* Vg = g_Vh + (size_t)bh * T_ * DH_;

    // ---- load Q tile (raw half copy), hoist Q fragments ----
#pragma unroll
    for (int rr = 0; rr < 2; rr++) {
        int i2  = tid + rr * 256;
        int row = i2 >> 3;
        int c8  = (i2 & 7) * 8;
        *(uint4*)&Qh[row * LDH + c8] =
            *(const uint4*)(Qg + (size_t)(q0 + row) * DH_ + c8);
    }
    __syncthreads();

    uint32_t qf[4][4];
    {
        uint32_t qaddr = (uint32_t)__cvta_generic_to_shared(
            &Qh[(wm * 16 + lrow) * LDH + lcol]);
#pragma unroll
        for (int ks = 0; ks < 4; ks++)
            ldmx4(qf[ks], qaddr + ks * 32);
    }

    float o[8][4];
#pragma unroll
    for (int ni = 0; ni < 8; ni++)
#pragma unroll
        for (int r = 0; r < 4; r++) o[ni][r] = 0.f;
    float rsum0 = 0.f, rsum1 = 0.f;

    const uint32_t kaddr0 = (uint32_t)__cvta_generic_to_shared(
        &Kh[(wh * 32 + lrow) * LDH + lcol]);
    const uint32_t kaddr1 = kaddr0 + 16 * LDH * 2;
    const uint32_t vaddr0 = (uint32_t)__cvta_generic_to_shared(
        &Vh[(wh * 32 + lrow) * LDH + lcol]);
    const uint32_t vaddr1 = vaddr0 + 16 * LDH * 2;

    for (int kt = 0; kt <= qt; kt++) {
        __syncthreads();
#pragma unroll
        for (int rr = 0; rr < 2; rr++) {
            int i2  = tid + rr * 256;
            int row = i2 >> 3;
            int c8  = (i2 & 7) * 8;
            const size_t goff = (size_t)(kt * 64 + row) * DH_ + c8;
            *(uint4*)&Kh[row * LDH + c8] = *(const uint4*)(Kg + goff);
            *(uint4*)&Vh[row * LDH + c8] = *(const uint4*)(Vg + goff);
        }
        __syncthreads();

        // ---- S = Q . K^T over this warp's 32 keys ----
        float s[4][4];
#pragma unroll
        for (int j = 0; j < 4; j++)
#pragma unroll
            for (int r = 0; r < 4; r++) s[j][r] = 0.f;

#pragma unroll
        for (int ks = 0; ks < 4; ks++) {
            uint32_t r0[4], r1[4];
            ldmx4(r0, kaddr0 + ks * 32);
            ldmx4(r1, kaddr1 + ks * 32);
            uint32_t b0[2] = { r0[0], r0[2] };
            uint32_t b1[2] = { r0[1], r0[3] };
            uint32_t b2[2] = { r1[0], r1[2] };
            uint32_t b3[2] = { r1[1], r1[3] };
            MMA_F16(s[0], qf[ks], b0);
            MMA_F16(s[1], qf[ks], b1);
            MMA_F16(s[2], qf[ks], b2);
            MMA_F16(s[3], qf[ks], b3);
        }

        // ---- exp + diag mask (masked -> 1.0) + rowsum; pack P ----
        const bool diag = (kt == qt);
        const int row0 = q0 + wm * 16 + gr;
        uint32_t pl[4], ph[4];
#pragma unroll
        for (int j = 0; j < 4; j++) {
            int colg = kt * 64 + wh * 32 + j * 8 + 2 * gc;
            float p0 = (diag && colg     > row0)     ? 1.f : __expf(s[j][0] * 0.125f);
            float p1 = (diag && colg + 1 > row0)     ? 1.f : __expf(s[j][1] * 0.125f);
            float p2 = (diag && colg     > row0 + 8) ? 1.f : __expf(s[j][2] * 0.125f);
            float p3 = (diag && colg + 1 > row0 + 8) ? 1.f : __expf(s[j][3] * 0.125f);
            rsum0 += p0 + p1;
            rsum1 += p2 + p3;
            pl[j] = h2u(__floats2half2_rn(p0, p1));
            ph[j] = h2u(__floats2half2_rn(p2, p3));
        }

        // ---- O += P . V ----
#pragma unroll
        for (int ks2 = 0; ks2 < 2; ks2++) {
            uint32_t a[4] = { pl[ks2 * 2], ph[ks2 * 2], pl[ks2 * 2 + 1], ph[ks2 * 2 + 1] };
            uint32_t vbase = (ks2 == 0) ? vaddr0 : vaddr1;
#pragma unroll
            for (int dg = 0; dg < 4; dg++) {
                uint32_t rv[4];
                ldmx4t(rv, vbase + dg * 32);
                uint32_t bA[2] = { rv[0], rv[1] };
                uint32_t bB[2] = { rv[2], rv[3] };
                MMA_F16(o[dg * 2],     a, bA);
                MMA_F16(o[dg * 2 + 1], a, bB);
            }
        }
    }

    // ---- rowsum reduce over gc lanes ----
    rsum0 += __shfl_xor_sync(0xffffffffu, rsum0, 1);
    rsum0 += __shfl_xor_sync(0xffffffffu, rsum0, 2);
    rsum1 += __shfl_xor_sync(0xffffffffu, rsum1, 1);
    rsum1 += __shfl_xor_sync(0xffffffffu, rsum1, 2);

    __syncthreads();
    if (wh == 0) {
        if (gc == 0) {
            redS[wm * 16 + gr]     = rsum0;
            redS[wm * 16 + 8 + gr] = rsum1;
        }
#pragma unroll
        for (int ni = 0; ni < 8; ni++) {
            int c = ni * 8 + 2 * gc;
            *(float2*)&redO[(wm * 16 + gr) * 64 + c]     = make_float2(o[ni][0], o[ni][1]);
            *(float2*)&redO[(wm * 16 + 8 + gr) * 64 + c] = make_float2(o[ni][2], o[ni][3]);
        }
    }
    __syncthreads();

    if (wh == 1) {
        const int b = bh / H_;
        const int h = bh - b * H_;
        const float tailN = (float)(T_ - (qt + 1) * 64);          // beyond-range count
        const float* vt = g_TS + ((size_t)bh * 33 + (qt + 1)) * DH_;  // beyond-range V sum
#pragma unroll
        for (int half_ = 0; half_ < 2; half_++) {
            int rl = wm * 16 + gr + 8 * half_;
            int qi = q0 + rl;
            float own = (half_ == 0) ? rsum0 : rsum1;
            float denom = own + redS[rl] + tailN;
            float inv = 1.f / denom;
            half* dst = g_AOh + ((size_t)(b * T_ + qi)) * D_ + h * DH_;
#pragma unroll
            for (int ni = 0; ni < 8; ni++) {
                int c = ni * 8 + 2 * gc;
                float2 red = *(const float2*)&redO[rl * 64 + c];
                float2 vtv = *(const float2*)&vt[c];
                float v0 = (o[ni][half_ * 2 + 0] + red.x + vtv.x) * inv;
                float v1 = (o[ni][half_ * 2 + 1] + red.y + vtv.y) * inv;
                *(half2*)&dst[c] = __floats2half2_rn(v0, v1);
            }
        }
    }
}

// ---------------- launch -----------------
extern "C" void kernel_launch(void* const* d_in, const int* in_sizes, int n_in,
                              void* d_out, int out_size)
{
    const float* X  = (const float*)d_in[0];
    const float* Wq = (const float*)d_in[1];
    const float* bq = (const float*)d_in[2];
    const float* Wk = (const float*)d_in[3];
    const float* bk = (const float*)d_in[4];
    const float* Wv = (const float*)d_in[5];
    const float* bv = (const float*)d_in[6];
    const float* Wo = (const float*)d_in[7];
    const float* bo = (const float*)d_in[8];
    float* out = (float*)d_out;

    const int total4 = XTOT4 + 4 * WTOT4;
    cvt_all<<<(total4 + 255) / 256, 256>>>(X, Wq, Wk, Wv, Wo);
    gemm_qkv_h<<<dim3(D_ / 64, M_ / 128, 3), 256>>>(bq, bk, bv);
    tiletot<<<dim3(32, 24), 64>>>();
    tilesuf<<<24, 64>>>();
    attn_tc<<<dim3(T_ / 64, B_ * H_), 256>>>();
    gemm_out_h<<<dim3(D_ / 64, M_ / 128), 256>>>(bo, out);
}

// round 11
// speedup vs baseline: 1.1174x; 1.0256x over previous
#include <cuda_runtime.h>
#include <cuda_fp16.h>
#include <cstdint>

#define B_   2
#define T_   2048
#define D_   768
#define H_   12
#define DH_  64
#define M_   (B_ * T_)   // 4096

// ---------------- scratch (static device globals; no allocation) ----------------
__device__ half  g_Xh [M_ * D_];             // X in fp16
__device__ half  g_Wqh[D_ * D_];
__device__ half  g_Wkh[D_ * D_];
__device__ half  g_Wvh[D_ * D_];
__device__ half  g_Woh[D_ * D_];
__device__ half  g_Qh [B_ * H_ * T_ * DH_];  // [B,H,T,Dh] fp16
__device__ half  g_Kh [B_ * H_ * T_ * DH_];
__device__ half  g_Vh [B_ * H_ * T_ * DH_];
__device__ half  g_AOh[M_ * D_];             // attention out, [B,T, H*Dh] fp16
__device__ float g_TS [24 * 33 * DH_];       // per-(bh,tile) V tile-suffix sums

// ---------------- helpers ----------------
#define MMA_F16(c, a, b)                                                         \
    asm volatile(                                                                \
        "mma.sync.aligned.m16n8k16.row.col.f32.f16.f16.f32 "                     \
        "{%0,%1,%2,%3},{%4,%5,%6,%7},{%8,%9},{%0,%1,%2,%3};"                     \
        : "+f"((c)[0]), "+f"((c)[1]), "+f"((c)[2]), "+f"((c)[3])                 \
        : "r"((a)[0]), "r"((a)[1]), "r"((a)[2]), "r"((a)[3]),                    \
          "r"((b)[0]), "r"((b)[1]))

__device__ __forceinline__ void ldmx4(uint32_t* r, uint32_t addr) {
    asm volatile("ldmatrix.sync.aligned.m8n8.x4.shared.b16 {%0,%1,%2,%3}, [%4];"
                 : "=r"(r[0]), "=r"(r[1]), "=r"(r[2]), "=r"(r[3]) : "r"(addr));
}
__device__ __forceinline__ void ldmx4t(uint32_t* r, uint32_t addr) {
    asm volatile("ldmatrix.sync.aligned.m8n8.x4.trans.shared.b16 {%0,%1,%2,%3}, [%4];"
                 : "=r"(r[0]), "=r"(r[1]), "=r"(r[2]), "=r"(r[3]) : "r"(addr));
}
__device__ __forceinline__ uint32_t h2u(half2 h) { return *reinterpret_cast<uint32_t*>(&h); }

__device__ __forceinline__ void cpa16(uint32_t saddr, const void* g) {
    asm volatile("cp.async.cg.shared.global [%0], [%1], 16;" :: "r"(saddr), "l"(g));
}
__device__ __forceinline__ void cp_commit() { asm volatile("cp.async.commit_group;"); }
template <int N>
__device__ __forceinline__ void cp_wait() { asm volatile("cp.async.wait_group %0;" :: "n"(N)); }

// ---------------- fp32 -> fp16 conversion of X and the 4 weight matrices --------
#define XTOT4 (M_ * D_ / 4)     // 786432
#define WTOT4 (D_ * D_ / 4)     // 147456

__global__ __launch_bounds__(256)
void cvt_all(const float* __restrict__ X,
             const float* __restrict__ Wq, const float* __restrict__ Wk,
             const float* __restrict__ Wv, const float* __restrict__ Wo)
{
    int i = blockIdx.x * 256 + threadIdx.x;
    const int total = XTOT4 + 4 * WTOT4;
    if (i >= total) return;
    const float* src; half* dst; int off;
    if (i < XTOT4) { src = X; dst = g_Xh; off = i; }
    else {
        int j = i - XTOT4;
        int w = j / WTOT4;
        off = j - w * WTOT4;
        src = (w == 0) ? Wq : (w == 1) ? Wk : (w == 2) ? Wv : Wo;
        dst = (w == 0) ? g_Wqh : (w == 1) ? g_Wkh : (w == 2) ? g_Wvh : g_Woh;
    }
    float4 v = ((const float4*)src)[off];
    uint2 u = make_uint2(h2u(__floats2half2_rn(v.x, v.y)),
                         h2u(__floats2half2_rn(v.z, v.w)));
    ((uint2*)dst)[off] = u;
}

// ---------------- fp16 tensor-core GEMM mainloop (128x64 tile, k-chunk 64) ------
#define LDA 72

__device__ __forceinline__
void gemm_h_mainloop(const half* __restrict__ A, const half* __restrict__ W,
                     float c[2][4][4], half* As, half* Ws)
{
    const int tid  = threadIdx.x;
    const int lane = tid & 31;
    const int wid  = tid >> 5;
    const int wm   = wid & 3;
    const int wn   = wid >> 2;
    const int m0   = blockIdx.y * 128;
    const int n0   = blockIdx.x * 64;
    const int lrow = lane & 15;
    const int lcol = (lane >> 4) * 8;

#pragma unroll
    for (int mi = 0; mi < 2; mi++)
#pragma unroll
        for (int j = 0; j < 4; j++)
#pragma unroll
            for (int r = 0; r < 4; r++) c[mi][j][r] = 0.f;

    const uint32_t aaddr0 = (uint32_t)__cvta_generic_to_shared(
        &As[(wm * 32 + lrow) * LDA + lcol]);
    const uint32_t aaddr1 = aaddr0 + 16 * LDA * 2;
    const uint32_t baddr  = (uint32_t)__cvta_generic_to_shared(
        &Ws[lrow * LDA + wn * 32 + lcol]);

    for (int kk = 0; kk < D_; kk += 64) {
#pragma unroll
        for (int r = 0; r < 4; r++) {
            int idx = tid + r * 256;
            int row = idx >> 3;
            int c8  = (idx & 7) * 8;
            *(uint4*)&As[row * LDA + c8] =
                *(const uint4*)(A + (size_t)(m0 + row) * D_ + kk + c8);
        }
#pragma unroll
        for (int r = 0; r < 2; r++) {
            int idx = tid + r * 256;
            int row = idx >> 3;
            int c8  = (idx & 7) * 8;
            *(uint4*)&Ws[row * LDA + c8] =
                *(const uint4*)(W + (size_t)(kk + row) * D_ + n0 + c8);
        }
        __syncthreads();

#pragma unroll
        for (int ks = 0; ks < 4; ks++) {
            uint32_t af[2][4];
            ldmx4(af[0], aaddr0 + ks * 32);
            ldmx4(af[1], aaddr1 + ks * 32);
#pragma unroll
            for (int ni = 0; ni < 2; ni++) {
                uint32_t bf[4];
                ldmx4t(bf, baddr + (ks * 16 * LDA + ni * 16) * 2);
                uint32_t b0[2] = { bf[0], bf[1] };
                uint32_t b1[2] = { bf[2], bf[3] };
                MMA_F16(c[0][ni * 2],     af[0], b0);
                MMA_F16(c[0][ni * 2 + 1], af[0], b1);
                MMA_F16(c[1][ni * 2],     af[1], b0);
                MMA_F16(c[1][ni * 2 + 1], af[1], b1);
            }
        }
        __syncthreads();
    }
}

// QKV projection: blockIdx.z selects matrix; epilogue scatters half into [B,H,T,Dh].
__global__ __launch_bounds__(256)
void gemm_qkv_h(const float* __restrict__ bq, const float* __restrict__ bk,
                const float* __restrict__ bv)
{
    __shared__ half As[128 * LDA];
    __shared__ half Ws[64 * LDA];

    const int z = blockIdx.z;
    const half*  W  = (z == 0) ? g_Wqh : (z == 1) ? g_Wkh : g_Wvh;
    const float* bb = (z == 0) ? bq    : (z == 1) ? bk    : bv;
    half*        Cd = (z == 0) ? g_Qh  : (z == 1) ? g_Kh  : g_Vh;

    float c[2][4][4];
    gemm_h_mainloop(g_Xh, W, c, As, Ws);

    const int lane = threadIdx.x & 31;
    const int wid  = threadIdx.x >> 5;
    const int wm   = wid & 3;
    const int wn   = wid >> 2;
    const int gr   = lane >> 2;
    const int gc   = lane & 3;
    const int m0   = blockIdx.y * 128;
    const int n0   = blockIdx.x * 64;

#pragma unroll
    for (int mi = 0; mi < 2; mi++) {
#pragma unroll
        for (int j = 0; j < 4; j++) {
            int col = n0 + wn * 32 + j * 8 + 2 * gc;
            float b0 = bb[col], b1 = bb[col + 1];
            int h  = col >> 6;
            int dh = col & 63;
#pragma unroll
            for (int hp = 0; hp < 2; hp++) {
                int row = m0 + wm * 32 + mi * 16 + gr + hp * 8;
                int bt  = row >> 11;
                int t   = row & (T_ - 1);
                half2 v = __floats2half2_rn(c[mi][j][hp * 2] + b0,
                                            c[mi][j][hp * 2 + 1] + b1);
                *(half2*)&Cd[((size_t)(bt * H_ + h) * T_ + t) * DH_ + dh] = v;
            }
        }
    }
}

// Output projection: AO(half) @ Wo + bo -> fp32 out.
__global__ __launch_bounds__(256)
void gemm_out_h(const float* __restrict__ bo, float* __restrict__ out)
{
    __shared__ half As[128 * LDA];
    __shared__ half Ws[64 * LDA];

    float c[2][4][4];
    gemm_h_mainloop(g_AOh, g_Woh, c, As, Ws);

    const int lane = threadIdx.x & 31;
    const int wid  = threadIdx.x >> 5;
    const int wm   = wid & 3;
    const int wn   = wid >> 2;
    const int gr   = lane >> 2;
    const int gc   = lane & 3;
    const int m0   = blockIdx.y * 128;
    const int n0   = blockIdx.x * 64;

#pragma unroll
    for (int mi = 0; mi < 2; mi++) {
#pragma unroll
        for (int j = 0; j < 4; j++) {
            int col = n0 + wn * 32 + j * 8 + 2 * gc;
            float b0 = bo[col], b1 = bo[col + 1];
#pragma unroll
            for (int hp = 0; hp < 2; hp++) {
                int row = m0 + wm * 32 + mi * 16 + gr + hp * 8;
                *(float2*)&out[(size_t)row * D_ + col] =
                    make_float2(c[mi][j][hp * 2] + b0, c[mi][j][hp * 2 + 1] + b1);
            }
        }
    }
}

// ---------------- fused V tile totals + suffix scan ----------------
// One block per bh: 16x64 threads compute 32 tile-total vectors into smem,
// 64 threads scan, all threads write TS[bh][0..32][d] coalesced.
__global__ __launch_bounds__(1024)
void vtail()
{
    __shared__ float ctot[32][64];
    __shared__ float suf[33][64];
    const int bh  = blockIdx.x;
    const int tid = threadIdx.x;
    const int d   = tid & 63;
    const int y   = tid >> 6;              // 0..15
    const half* V = g_Vh + (size_t)bh * T_ * DH_ + d;

#pragma unroll
    for (int rep = 0; rep < 2; rep++) {
        const int tl = y + rep * 16;
        const half* Vp = V + (size_t)tl * 64 * DH_;
        float sum = 0.f;
#pragma unroll 16
        for (int t = 0; t < 64; t++)
            sum += __half2float(Vp[(size_t)t * DH_]);
        ctot[tl][d] = sum;
    }
    __syncthreads();

    if (y == 0) {
        float s = 0.f;
        suf[32][d] = 0.f;
#pragma unroll
        for (int t = 31; t >= 0; t--) {
            s += ctot[t][d];
            suf[t][d] = s;
        }
    }
    __syncthreads();

    float* TS = g_TS + (size_t)bh * 33 * DH_;
#pragma unroll
    for (int i = tid; i < 33 * 64; i += 1024)
        TS[i] = suf[i >> 6][i & 63];
}

// ---------------- fp16 tensor-core causal attention (zero-fill semantics) -------
// 8 warps = 4 (m16 q-row groups) x 2 (32-key halves). Masked diag entries get
// p=1; beyond-range tiles corrected by TS[bh][qt+1] and count T-(qt+1)*64.
// K/V tiles double-buffered via cp.async.
#define LDH 72
#define KV_SZ (64 * LDH)                        // halves per K or V stage
#define ATT_SMEM ((64 * LDH + 4 * KV_SZ) * 2 + 4 * 16 * 64 * 4 + 64 * 4)  // 62720 B

__global__ __launch_bounds__(256, 2)
void attn_tc()
{
    extern __shared__ __align__(16) uint8_t smraw[];
    half* Qh = (half*)smraw;                  // 64 x LDH
    half* Kh = Qh + 64 * LDH;                 // 2 stages
    half* Vh = Kh + 2 * KV_SZ;                // 2 stages
    float* redO = (float*)(Vh + 2 * KV_SZ);   // 4*16 x 64
    float* redS = redO + 4 * 16 * 64;

    const int tid  = threadIdx.x;
    const int lane = tid & 31;
    const int wid  = tid >> 5;
    const int wm   = wid & 3;
    const int wh   = wid >> 2;
    const int gr   = lane >> 2;
    const int gc   = lane & 3;
    const int lrow = lane & 15;
    const int lcol = (lane >> 4) * 8;

    const int bh = blockIdx.y;
    const int qt = gridDim.x - 1 - blockIdx.x;    // heavy tiles first
    const int q0 = qt * 64;

    const half* Qg = g_Qh + (size_t)bh * T_ * DH_;
    const half* Kg = g_Kh + (size_t)bh * T_ * DH_;
    const half* Vg = g_Vh + (size_t)bh * T_ * DH_;

    const uint32_t qsb = (uint32_t)__cvta_generic_to_shared(Qh);
    const uint32_t ksb = (uint32_t)__cvta_generic_to_shared(Kh);
    const uint32_t vsb = (uint32_t)__cvta_generic_to_shared(Vh);

    // per-thread tile-load coordinates (64 rows x 8 uint4-cols; 2 chunks/thread)
    const int c8    = (tid & 7) * 8;
    const int row_a = (tid + 0)   >> 3;
    const int row_b = (tid + 256) >> 3;

    // ---- group 0: Q tile + K/V stage 0 ----
    cpa16(qsb + (row_a * LDH + c8) * 2, Qg + (size_t)(q0 + row_a) * DH_ + c8);
    cpa16(qsb + (row_b * LDH + c8) * 2, Qg + (size_t)(q0 + row_b) * DH_ + c8);
    cpa16(ksb + (row_a * LDH + c8) * 2, Kg + (size_t)row_a * DH_ + c8);
    cpa16(ksb + (row_b * LDH + c8) * 2, Kg + (size_t)row_b * DH_ + c8);
    cpa16(vsb + (row_a * LDH + c8) * 2, Vg + (size_t)row_a * DH_ + c8);
    cpa16(vsb + (row_b * LDH + c8) * 2, Vg + (size_t)row_b * DH_ + c8);
    cp_commit();

    float o[8][4];
#pragma unroll
    for (int ni = 0; ni < 8; ni++)
#pragma unroll
        for (int r = 0; r < 4; r++) o[ni][r] = 0.f;
    float rsum0 = 0.f, rsum1 = 0.f;
    uint32_t qf[4][4];

    const uint32_t kaddr_l = (uint32_t)__cvta_generic_to_shared(
        &Kh[(wh * 32 + lrow) * LDH + lcol]);
    const uint32_t vaddr_l = (uint32_t)__cvta_generic_to_shared(
        &Vh[(wh * 32 + lrow) * LDH + lcol]);

    for (int kt = 0; kt <= qt; kt++) {
        if (kt + 1 <= qt) {
            const uint32_t so = ((kt + 1) & 1) * (KV_SZ * 2);
            const size_t ga = (size_t)((kt + 1) * 64 + row_a) * DH_ + c8;
            const size_t gb = (size_t)((kt + 1) * 64 + row_b) * DH_ + c8;
            cpa16(ksb + so + (row_a * LDH + c8) * 2, Kg + ga);
            cpa16(ksb + so + (row_b * LDH + c8) * 2, Kg + gb);
            cpa16(vsb + so + (row_a * LDH + c8) * 2, Vg + ga);
            cpa16(vsb + so + (row_b * LDH + c8) * 2, Vg + gb);
            cp_commit();
            cp_wait<1>();
        } else {
            cp_wait<0>();
        }
        __syncthreads();

        if (kt == 0) {
            uint32_t qaddr = qsb + ((wm * 16 + lrow) * LDH + lcol) * 2;
#pragma unroll
            for (int ks = 0; ks < 4; ks++)
                ldmx4(qf[ks], qaddr + ks * 32);
        }

        const uint32_t kaddr0 = kaddr_l + (kt & 1) * (KV_SZ * 2);
        const uint32_t kaddr1 = kaddr0 + 16 * LDH * 2;
        const uint32_t vaddr0 = vaddr_l + (kt & 1) * (KV_SZ * 2);
        const uint32_t vaddr1 = vaddr0 + 16 * LDH * 2;

        // ---- S = Q . K^T over this warp's 32 keys ----
        float s[4][4];
#pragma unroll
        for (int j = 0; j < 4; j++)
#pragma unroll
            for (int r = 0; r < 4; r++) s[j][r] = 0.f;

#pragma unroll
        for (int ks = 0; ks < 4; ks++) {
            uint32_t r0[4], r1[4];
            ldmx4(r0, kaddr0 + ks * 32);
            ldmx4(r1, kaddr1 + ks * 32);
            uint32_t b0[2] = { r0[0], r0[2] };
            uint32_t b1[2] = { r0[1], r0[3] };
            uint32_t b2[2] = { r1[0], r1[2] };
            uint32_t b3[2] = { r1[1], r1[3] };
            MMA_F16(s[0], qf[ks], b0);
            MMA_F16(s[1], qf[ks], b1);
            MMA_F16(s[2], qf[ks], b2);
            MMA_F16(s[3], qf[ks], b3);
        }

        // ---- exp + diag mask (masked -> 1.0) + rowsum; pack P ----
        const bool diag = (kt == qt);
        const int row0 = q0 + wm * 16 + gr;
        uint32_t pl[4], ph[4];
#pragma unroll
        for (int j = 0; j < 4; j++) {
            int colg = kt * 64 + wh * 32 + j * 8 + 2 * gc;
            float p0 = (diag && colg     > row0)     ? 1.f : __expf(s[j][0] * 0.125f);
            float p1 = (diag && colg + 1 > row0)     ? 1.f : __expf(s[j][1] * 0.125f);
            float p2 = (diag && colg     > row0 + 8) ? 1.f : __expf(s[j][2] * 0.125f);
            float p3 = (diag && colg + 1 > row0 + 8) ? 1.f : __expf(s[j][3] * 0.125f);
            rsum0 += p0 + p1;
            rsum1 += p2 + p3;
            pl[j] = h2u(__floats2half2_rn(p0, p1));
            ph[j] = h2u(__floats2half2_rn(p2, p3));
        }

        // ---- O += P . V ----
#pragma unroll
        for (int ks2 = 0; ks2 < 2; ks2++) {
            uint32_t a[4] = { pl[ks2 * 2], ph[ks2 * 2], pl[ks2 * 2 + 1], ph[ks2 * 2 + 1] };
            uint32_t vbase = (ks2 == 0) ? vaddr0 : vaddr1;
#pragma unroll
            for (int dg = 0; dg < 4; dg++) {
                uint32_t rv[4];
                ldmx4t(rv, vbase + dg * 32);
                uint32_t bA[2] = { rv[0], rv[1] };
                uint32_t bB[2] = { rv[2], rv[3] };
                MMA_F16(o[dg * 2],     a, bA);
                MMA_F16(o[dg * 2 + 1], a, bB);
            }
        }
        __syncthreads();    // all reads of this stage done before next prefetch reuses it
    }

    // ---- rowsum reduce over gc lanes ----
    rsum0 += __shfl_xor_sync(0xffffffffu, rsum0, 1);
    rsum0 += __shfl_xor_sync(0xffffffffu, rsum0, 2);
    rsum1 += __shfl_xor_sync(0xffffffffu, rsum1, 1);
    rsum1 += __shfl_xor_sync(0xffffffffu, rsum1, 2);

    if (wh == 0) {
        if (gc == 0) {
            redS[wm * 16 + gr]     = rsum0;
            redS[wm * 16 + 8 + gr] = rsum1;
        }
#pragma unroll
        for (int ni = 0; ni < 8; ni++) {
            int c = ni * 8 + 2 * gc;
            *(float2*)&redO[(wm * 16 + gr) * 64 + c]     = make_float2(o[ni][0], o[ni][1]);
            *(float2*)&redO[(wm * 16 + 8 + gr) * 64 + c] = make_float2(o[ni][2], o[ni][3]);
        }
    }
    __syncthreads();

    if (wh == 1) {
        const int b = bh / H_;
        const int h = bh - b * H_;
        const float tailN = (float)(T_ - (qt + 1) * 64);
        const float* vt = g_TS + ((size_t)bh * 33 + (qt + 1)) * DH_;
#pragma unroll
        for (int half_ = 0; half_ < 2; half_++) {
            int rl = wm * 16 + gr + 8 * half_;
            int qi = q0 + rl;
            float own = (half_ == 0) ? rsum0 : rsum1;
            float denom = own + redS[rl] + tailN;
            float inv = 1.f / denom;
            half* dst = g_AOh + ((size_t)(b * T_ + qi)) * D_ + h * DH_;
#pragma unroll
            for (int ni = 0; ni < 8; ni++) {
                int c = ni * 8 + 2 * gc;
                float2 red = *(const float2*)&redO[rl * 64 + c];
                float2 vtv = *(const float2*)&vt[c];
                float v0 = (o[ni][half_ * 2 + 0] + red.x + vtv.x) * inv;
                float v1 = (o[ni][half_ * 2 + 1] + red.y + vtv.y) * inv;
                *(half2*)&dst[c] = __floats2half2_rn(v0, v1);
            }
        }
    }
}

// ---------------- launch -----------------
extern "C" void kernel_launch(void* const* d_in, const int* in_sizes, int n_in,
                              void* d_out, int out_size)
{
    const float* X  = (const float*)d_in[0];
    const float* Wq = (const float*)d_in[1];
    const float* bq = (const float*)d_in[2];
    const float* Wk = (const float*)d_in[3];
    const float* bk = (const float*)d_in[4];
    const float* Wv = (const float*)d_in[5];
    const float* bv = (const float*)d_in[6];
    const float* Wo = (const float*)d_in[7];
    const float* bo = (const float*)d_in[8];
    float* out = (float*)d_out;

    cudaFuncSetAttribute(attn_tc, cudaFuncAttributeMaxDynamicSharedMemorySize, ATT_SMEM);

    const int total4 = XTOT4 + 4 * WTOT4;
    cvt_all<<<(total4 + 255) / 256, 256>>>(X, Wq, Wk, Wv, Wo);
    gemm_qkv_h<<<dim3(D_ / 64, M_ / 128, 3), 256>>>(bq, bk, bv);
    vtail<<<24, 1024>>>();
    attn_tc<<<dim3(T_ / 64, B_ * H_), 256, ATT_SMEM>>>();
    gemm_out_h<<<dim3(D_ / 64, M_ / 128), 256>>>(bo, out);
}

// round 13
// speedup vs baseline: 1.2213x; 1.0930x over previous
#include <cuda_runtime.h>
#include <cuda_fp16.h>
#include <cstdint>

#define B_   2
#define T_   2048
#define D_   768
#define H_   12
#define DH_  64
#define M_   (B_ * T_)   // 4096

// softmax scale folded into Q: 0.125 * log2(e)
#define QSCALE 0.18033688011112042f

// ---------------- scratch (static device globals; no allocation) ----------------
__device__ half  g_Xh [M_ * D_];             // X in fp16
__device__ half  g_Wqh[D_ * D_];
__device__ half  g_Wkh[D_ * D_];
__device__ half  g_Wvh[D_ * D_];
__device__ half  g_Woh[D_ * D_];
__device__ half  g_Qh [B_ * H_ * T_ * DH_];  // [B,H,T,Dh] fp16 (pre-scaled)
__device__ half  g_Kh [B_ * H_ * T_ * DH_];
__device__ half  g_Vh [B_ * H_ * T_ * DH_];
__device__ half  g_AOh[M_ * D_];             // attention out, [B,T, H*Dh] fp16
__device__ float g_TS [24 * 33 * DH_];       // per-(bh,tile) V tile-suffix sums

// ---------------- helpers ----------------
#define MMA_F16(c, a, b)                                                         \
    asm volatile(                                                                \
        "mma.sync.aligned.m16n8k16.row.col.f32.f16.f16.f32 "                     \
        "{%0,%1,%2,%3},{%4,%5,%6,%7},{%8,%9},{%0,%1,%2,%3};"                     \
        : "+f"((c)[0]), "+f"((c)[1]), "+f"((c)[2]), "+f"((c)[3])                 \
        : "r"((a)[0]), "r"((a)[1]), "r"((a)[2]), "r"((a)[3]),                    \
          "r"((b)[0]), "r"((b)[1]))

__device__ __forceinline__ void ldmx4(uint32_t* r, uint32_t addr) {
    asm volatile("ldmatrix.sync.aligned.m8n8.x4.shared.b16 {%0,%1,%2,%3}, [%4];"
                 : "=r"(r[0]), "=r"(r[1]), "=r"(r[2]), "=r"(r[3]) : "r"(addr));
}
__device__ __forceinline__ void ldmx4t(uint32_t* r, uint32_t addr) {
    asm volatile("ldmatrix.sync.aligned.m8n8.x4.trans.shared.b16 {%0,%1,%2,%3}, [%4];"
                 : "=r"(r[0]), "=r"(r[1]), "=r"(r[2]), "=r"(r[3]) : "r"(addr));
}
__device__ __forceinline__ uint32_t h2u(half2 h) { return *reinterpret_cast<uint32_t*>(&h); }

__device__ __forceinline__ void cpa16(uint32_t saddr, const void* g) {
    asm volatile("cp.async.cg.shared.global [%0], [%1], 16;" :: "r"(saddr), "l"(g));
}
__device__ __forceinline__ void cp_commit() { asm volatile("cp.async.commit_group;"); }
template <int N>
__device__ __forceinline__ void cp_wait() { asm volatile("cp.async.wait_group %0;" :: "n"(N)); }

// ---------------- fp32 -> fp16 conversion of X and the 4 weight matrices --------
#define XTOT4 (M_ * D_ / 4)     // 786432
#define WTOT4 (D_ * D_ / 4)     // 147456

__global__ __launch_bounds__(256)
void cvt_all(const float* __restrict__ X,
             const float* __restrict__ Wq, const float* __restrict__ Wk,
             const float* __restrict__ Wv, const float* __restrict__ Wo)
{
    int i = blockIdx.x * 256 + threadIdx.x;
    const int total = XTOT4 + 4 * WTOT4;
    if (i >= total) return;
    const float* src; half* dst; int off;
    if (i < XTOT4) { src = X; dst = g_Xh; off = i; }
    else {
        int j = i - XTOT4;
        int w = j / WTOT4;
        off = j - w * WTOT4;
        src = (w == 0) ? Wq : (w == 1) ? Wk : (w == 2) ? Wv : Wo;
        dst = (w == 0) ? g_Wqh : (w == 1) ? g_Wkh : (w == 2) ? g_Wvh : g_Woh;
    }
    float4 v = ((const float4*)src)[off];
    uint2 u = make_uint2(h2u(__floats2half2_rn(v.x, v.y)),
                         h2u(__floats2half2_rn(v.z, v.w)));
    ((uint2*)dst)[off] = u;
}

// ---------------- fp16 tensor-core GEMM mainloop (128x64 tile, k-chunk 64) ------
#define LDA 72

__device__ __forceinline__
void gemm_h_mainloop(const half* __restrict__ A, const half* __restrict__ W,
                     float c[2][4][4], half* As, half* Ws)
{
    const int tid  = threadIdx.x;
    const int lane = tid & 31;
    const int wid  = tid >> 5;
    const int wm   = wid & 3;
    const int wn   = wid >> 2;
    const int m0   = blockIdx.y * 128;
    const int n0   = blockIdx.x * 64;
    const int lrow = lane & 15;
    const int lcol = (lane >> 4) * 8;

#pragma unroll
    for (int mi = 0; mi < 2; mi++)
#pragma unroll
        for (int j = 0; j < 4; j++)
#pragma unroll
            for (int r = 0; r < 4; r++) c[mi][j][r] = 0.f;

    const uint32_t aaddr0 = (uint32_t)__cvta_generic_to_shared(
        &As[(wm * 32 + lrow) * LDA + lcol]);
    const uint32_t aaddr1 = aaddr0 + 16 * LDA * 2;
    const uint32_t baddr  = (uint32_t)__cvta_generic_to_shared(
        &Ws[lrow * LDA + wn * 32 + lcol]);

    for (int kk = 0; kk < D_; kk += 64) {
#pragma unroll
        for (int r = 0; r < 4; r++) {
            int idx = tid + r * 256;
            int row = idx >> 3;
            int c8  = (idx & 7) * 8;
            *(uint4*)&As[row * LDA + c8] =
                *(const uint4*)(A + (size_t)(m0 + row) * D_ + kk + c8);
        }
#pragma unroll
        for (int r = 0; r < 2; r++) {
            int idx = tid + r * 256;
            int row = idx >> 3;
            int c8  = (idx & 7) * 8;
            *(uint4*)&Ws[row * LDA + c8] =
                *(const uint4*)(W + (size_t)(kk + row) * D_ + n0 + c8);
        }
        __syncthreads();

#pragma unroll
        for (int ks = 0; ks < 4; ks++) {
            uint32_t af[2][4];
            ldmx4(af[0], aaddr0 + ks * 32);
            ldmx4(af[1], aaddr1 + ks * 32);
#pragma unroll
            for (int ni = 0; ni < 2; ni++) {
                uint32_t bf[4];
                ldmx4t(bf, baddr + (ks * 16 * LDA + ni * 16) * 2);
                uint32_t b0[2] = { bf[0], bf[1] };
                uint32_t b1[2] = { bf[2], bf[3] };
                MMA_F16(c[0][ni * 2],     af[0], b0);
                MMA_F16(c[0][ni * 2 + 1], af[0], b1);
                MMA_F16(c[1][ni * 2],     af[1], b0);
                MMA_F16(c[1][ni * 2 + 1], af[1], b1);
            }
        }
        __syncthreads();
    }
}

// QKV projection: blockIdx.z selects matrix; epilogue scatters half into [B,H,T,Dh].
// Q is pre-scaled by QSCALE so attention can use exp2 directly.
__global__ __launch_bounds__(256)
void gemm_qkv_h(const float* __restrict__ bq, const float* __restrict__ bk,
                const float* __restrict__ bv)
{
    __shared__ half As[128 * LDA];
    __shared__ half Ws[64 * LDA];

    const int z = blockIdx.z;
    const half*  W  = (z == 0) ? g_Wqh : (z == 1) ? g_Wkh : g_Wvh;
    const float* bb = (z == 0) ? bq    : (z == 1) ? bk    : bv;
    half*        Cd = (z == 0) ? g_Qh  : (z == 1) ? g_Kh  : g_Vh;
    const float  sc = (z == 0) ? QSCALE : 1.f;

    float c[2][4][4];
    gemm_h_mainloop(g_Xh, W, c, As, Ws);

    const int lane = threadIdx.x & 31;
    const int wid  = threadIdx.x >> 5;
    const int wm   = wid & 3;
    const int wn   = wid >> 2;
    const int gr   = lane >> 2;
    const int gc   = lane & 3;
    const int m0   = blockIdx.y * 128;
    const int n0   = blockIdx.x * 64;

#pragma unroll
    for (int mi = 0; mi < 2; mi++) {
#pragma unroll
        for (int j = 0; j < 4; j++) {
            int col = n0 + wn * 32 + j * 8 + 2 * gc;
            float b0 = bb[col], b1 = bb[col + 1];
            int h  = col >> 6;
            int dh = col & 63;
#pragma unroll
            for (int hp = 0; hp < 2; hp++) {
                int row = m0 + wm * 32 + mi * 16 + gr + hp * 8;
                int bt  = row >> 11;
                int t   = row & (T_ - 1);
                half2 v = __floats2half2_rn((c[mi][j][hp * 2] + b0) * sc,
                                            (c[mi][j][hp * 2 + 1] + b1) * sc);
                *(half2*)&Cd[((size_t)(bt * H_ + h) * T_ + t) * DH_ + dh] = v;
            }
        }
    }
}

// Output projection: AO(half) @ Wo + bo -> fp32 out.
__global__ __launch_bounds__(256)
void gemm_out_h(const float* __restrict__ bo, float* __restrict__ out)
{
    __shared__ half As[128 * LDA];
    __shared__ half Ws[64 * LDA];

    float c[2][4][4];
    gemm_h_mainloop(g_AOh, g_Woh, c, As, Ws);

    const int lane = threadIdx.x & 31;
    const int wid  = threadIdx.x >> 5;
    const int wm   = wid & 3;
    const int wn   = wid >> 2;
    const int gr   = lane >> 2;
    const int gc   = lane & 3;
    const int m0   = blockIdx.y * 128;
    const int n0   = blockIdx.x * 64;

#pragma unroll
    for (int mi = 0; mi < 2; mi++) {
#pragma unroll
        for (int j = 0; j < 4; j++) {
            int col = n0 + wn * 32 + j * 8 + 2 * gc;
            float b0 = bo[col], b1 = bo[col + 1];
#pragma unroll
            for (int hp = 0; hp < 2; hp++) {
                int row = m0 + wm * 32 + mi * 16 + gr + hp * 8;
                *(float2*)&out[(size_t)row * D_ + col] =
                    make_float2(c[mi][j][hp * 2] + b0, c[mi][j][hp * 2 + 1] + b1);
            }
        }
    }
}

// ---------------- fused V tile totals + suffix scan ----------------
__global__ __launch_bounds__(1024)
void vtail()
{
    __shared__ float ctot[32][64];
    __shared__ float suf[33][64];
    const int bh  = blockIdx.x;
    const int tid = threadIdx.x;
    const int d   = tid & 63;
    const int y   = tid >> 6;              // 0..15
    const half* V = g_Vh + (size_t)bh * T_ * DH_ + d;

#pragma unroll
    for (int rep = 0; rep < 2; rep++) {
        const int tl = y + rep * 16;
        const half* Vp = V + (size_t)tl * 64 * DH_;
        float sum = 0.f;
#pragma unroll 16
        for (int t = 0; t < 64; t++)
            sum += __half2float(Vp[(size_t)t * DH_]);
        ctot[tl][d] = sum;
    }
    __syncthreads();

    if (y == 0) {
        float s = 0.f;
        suf[32][d] = 0.f;
#pragma unroll
        for (int t = 31; t >= 0; t--) {
            s += ctot[t][d];
            suf[t][d] = s;
        }
    }
    __syncthreads();

    float* TS = g_TS + (size_t)bh * 33 * DH_;
#pragma unroll
    for (int i = tid; i < 33 * 64; i += 1024)
        TS[i] = suf[i >> 6][i & 63];
}

// ---------------- fp16 tensor-core causal attention (zero-fill semantics) -------
// 8 warps = 4 (m16 q-row groups) x 2 (32-key halves). Diagonal tile peeled out
// of the mainloop (mask-free body); masked entries on the diag get p=1.
// 3-stage cp.async ring, ONE barrier per iteration.
#define LDH 72
#define KV_SZ (64 * LDH)                        // halves per K or V stage
#define ATT_SMEM ((64 * LDH + 6 * KV_SZ) * 2 + 4 * 16 * 64 * 4 + 64 * 4)  // 81152 B

__global__ __launch_bounds__(256, 2)
void attn_tc()
{
    extern __shared__ __align__(16) uint8_t smraw[];
    half* Qh = (half*)smraw;                  // 64 x LDH
    half* Kh = Qh + 64 * LDH;                 // 3 stages
    half* Vh = Kh + 3 * KV_SZ;                // 3 stages
    float* redO = (float*)(Vh + 3 * KV_SZ);   // 4*16 x 64
    float* redS = redO + 4 * 16 * 64;

    const int tid  = threadIdx.x;
    const int lane = tid & 31;
    const int wid  = tid >> 5;
    const int wm   = wid & 3;
    const int wh   = wid >> 2;
    const int gr   = lane >> 2;
    const int gc   = lane & 3;
    const int lrow = lane & 15;
    const int lcol = (lane >> 4) * 8;

    const int bh = blockIdx.y;
    const int qt = gridDim.x - 1 - blockIdx.x;    // heavy tiles first
    const int q0 = qt * 64;

    const half* Qg = g_Qh + (size_t)bh * T_ * DH_;
    const half* Kg = g_Kh + (size_t)bh * T_ * DH_;
    const half* Vg = g_Vh + (size_t)bh * T_ * DH_;

    const uint32_t qsb = (uint32_t)__cvta_generic_to_shared(Qh);
    const uint32_t ksb = (uint32_t)__cvta_generic_to_shared(Kh);
    const uint32_t vsb = (uint32_t)__cvta_generic_to_shared(Vh);

    // per-thread tile-load coordinates (64 rows x 8 uint4-cols; 2 chunks/thread)
    const int c8    = (tid & 7) * 8;
    const int row_a = (tid + 0)   >> 3;
    const int row_b = (tid + 256) >> 3;

    auto prefetch = [&](int kt, int st) {
        const uint32_t so = (uint32_t)st * (KV_SZ * 2);
        const size_t ga = (size_t)(kt * 64 + row_a) * DH_ + c8;
        const size_t gb = (size_t)(kt * 64 + row_b) * DH_ + c8;
        cpa16(ksb + so + (row_a * LDH + c8) * 2, Kg + ga);
        cpa16(ksb + so + (row_b * LDH + c8) * 2, Kg + gb);
        cpa16(vsb + so + (row_a * LDH + c8) * 2, Vg + ga);
        cpa16(vsb + so + (row_b * LDH + c8) * 2, Vg + gb);
        cp_commit();
    };

    // ---- group 0: Q tile + K/V stage 0; group 1: stage 1 (if needed) ----
    cpa16(qsb + (row_a * LDH + c8) * 2, Qg + (size_t)(q0 + row_a) * DH_ + c8);
    cpa16(qsb + (row_b * LDH + c8) * 2, Qg + (size_t)(q0 + row_b) * DH_ + c8);
    cpa16(ksb + (row_a * LDH + c8) * 2, Kg + (size_t)row_a * DH_ + c8);
    cpa16(ksb + (row_b * LDH + c8) * 2, Kg + (size_t)row_b * DH_ + c8);
    cpa16(vsb + (row_a * LDH + c8) * 2, Vg + (size_t)row_a * DH_ + c8);
    cpa16(vsb + (row_b * LDH + c8) * 2, Vg + (size_t)row_b * DH_ + c8);
    cp_commit();
    if (qt >= 1) prefetch(1, 1);

    float o[8][4];
#pragma unroll
    for (int ni = 0; ni < 8; ni++)
#pragma unroll
        for (int r = 0; r < 4; r++) o[ni][r] = 0.f;
    float rsum0 = 0.f, rsum1 = 0.f;
    uint32_t qf[4][4];

    const uint32_t kaddr_l = (uint32_t)__cvta_generic_to_shared(
        &Kh[(wh * 32 + lrow) * LDH + lcol]);
    const uint32_t vaddr_l = (uint32_t)__cvta_generic_to_shared(
        &Vh[(wh * 32 + lrow) * LDH + lcol]);
    const uint32_t qaddr = qsb + ((wm * 16 + lrow) * LDH + lcol) * 2;

    // body: S -> exp(2^) -> PV for one 64-key tile in stage st
    auto body = [&](int kt, int st, bool diag) {
        const uint32_t kaddr0 = kaddr_l + (uint32_t)st * (KV_SZ * 2);
        const uint32_t kaddr1 = kaddr0 + 16 * LDH * 2;
        const uint32_t vaddr0 = vaddr_l + (uint32_t)st * (KV_SZ * 2);
        const uint32_t vaddr1 = vaddr0 + 16 * LDH * 2;

        float s[4][4];
#pragma unroll
        for (int j = 0; j < 4; j++)
#pragma unroll
            for (int r = 0; r < 4; r++) s[j][r] = 0.f;

#pragma unroll
        for (int ks = 0; ks < 4; ks++) {
            uint32_t r0[4], r1[4];
            ldmx4(r0, kaddr0 + ks * 32);
            ldmx4(r1, kaddr1 + ks * 32);
            uint32_t b0[2] = { r0[0], r0[2] };
            uint32_t b1[2] = { r0[1], r0[3] };
            uint32_t b2[2] = { r1[0], r1[2] };
            uint32_t b3[2] = { r1[1], r1[3] };
            MMA_F16(s[0], qf[ks], b0);
            MMA_F16(s[1], qf[ks], b1);
            MMA_F16(s[2], qf[ks], b2);
            MMA_F16(s[3], qf[ks], b3);
        }

        uint32_t pl[4], ph[4];
        const int row0 = q0 + wm * 16 + gr;
#pragma unroll
        for (int j = 0; j < 4; j++) {
            float p0 = exp2f(s[j][0]);
            float p1 = exp2f(s[j][1]);
            float p2 = exp2f(s[j][2]);
            float p3 = exp2f(s[j][3]);
            if (diag) {
                int colg = kt * 64 + wh * 32 + j * 8 + 2 * gc;
                if (colg     > row0)     p0 = 1.f;
                if (colg + 1 > row0)     p1 = 1.f;
                if (colg     > row0 + 8) p2 = 1.f;
                if (colg + 1 > row0 + 8) p3 = 1.f;
            }
            rsum0 += p0 + p1;
            rsum1 += p2 + p3;
            pl[j] = h2u(__floats2half2_rn(p0, p1));
            ph[j] = h2u(__floats2half2_rn(p2, p3));
        }

#pragma unroll
        for (int ks2 = 0; ks2 < 2; ks2++) {
            uint32_t a[4] = { pl[ks2 * 2], ph[ks2 * 2], pl[ks2 * 2 + 1], ph[ks2 * 2 + 1] };
            uint32_t vbase = (ks2 == 0) ? vaddr0 : vaddr1;
#pragma unroll
            for (int dg = 0; dg < 4; dg++) {
                uint32_t rv[4];
                ldmx4t(rv, vbase + dg * 32);
                uint32_t bA[2] = { rv[0], rv[1] };
                uint32_t bB[2] = { rv[2], rv[3] };
                MMA_F16(o[dg * 2],     a, bA);
                MMA_F16(o[dg * 2 + 1], a, bB);
            }
        }
    };

    // ---- main loop: mask-free tiles kt = 0 .. qt-1 ----
    int stg = 0;
    for (int kt = 0; kt < qt; kt++) {
        cp_wait<1>();          // stage kt ready (group kt+1 may be in flight)
        __syncthreads();       // all warps done with iteration kt-1
        int st2 = stg + 2; if (st2 >= 3) st2 -= 3;
        if (kt + 2 <= qt) prefetch(kt + 2, st2);
        if (kt == 0) {
#pragma unroll
            for (int ks = 0; ks < 4; ks++)
                ldmx4(qf[ks], qaddr + ks * 32);
        }
        body(kt, stg, false);
        stg = (stg == 2) ? 0 : stg + 1;
    }

    // ---- diagonal tile kt = qt (masked; masked entries -> 1.0) ----
    cp_wait<0>();
    __syncthreads();
    if (qt == 0) {
#pragma unroll
        for (int ks = 0; ks < 4; ks++)
            ldmx4(qf[ks], qaddr + ks * 32);
    }
    body(qt, stg, true);

    // ---- rowsum reduce over gc lanes ----
    rsum0 += __shfl_xor_sync(0xffffffffu, rsum0, 1);
    rsum0 += __shfl_xor_sync(0xffffffffu, rsum0, 2);
    rsum1 += __shfl_xor_sync(0xffffffffu, rsum1, 1);
    rsum1 += __shfl_xor_sync(0xffffffffu, rsum1, 2);

    __syncthreads();
    if (wh == 0) {
        if (gc == 0) {
            redS[wm * 16 + gr]     = rsum0;
            redS[wm * 16 + 8 + gr] = rsum1;
        }
#pragma unroll
        for (int ni = 0; ni < 8; ni++) {
            int c = ni * 8 + 2 * gc;
            *(float2*)&redO[(wm * 16 + gr) * 64 + c]     = make_float2(o[ni][0], o[ni][1]);
            *(float2*)&redO[(wm * 16 + 8 + gr) * 64 + c] = make_float2(o[ni][2], o[ni][3]);
        }
    }
    __syncthreads();

    if (wh == 1) {
        const int b = bh / H_;
        const int h = bh - b * H_;
        const float tailN = (float)(T_ - (qt + 1) * 64);
        const float* vt = g_TS + ((size_t)bh * 33 + (qt + 1)) * DH_;
#pragma unroll
        for (int half_ = 0; half_ < 2; half_++) {
            int rl = wm * 16 + gr + 8 * half_;
            int qi = q0 + rl;
            float own = (half_ == 0) ? rsum0 : rsum1;
            float denom = own + redS[rl] + tailN;
            float inv = 1.f / denom;
            half* dst = g_AOh + ((size_t)(b * T_ + qi)) * D_ + h * DH_;
#pragma unroll
            for (int ni = 0; ni < 8; ni++) {
                int c = ni * 8 + 2 * gc;
                float2 red = *(const float2*)&redO[rl * 64 + c];
                float2 vtv = *(const float2*)&vt[c];
                float v0 = (o[ni][half_ * 2 + 0] + red.x + vtv.x) * inv;
                float v1 = (o[ni][half_ * 2 + 1] + red.y + vtv.y) * inv;
                *(half2*)&dst[c] = __floats2half2_rn(v0, v1);
            }
        }
    }
}

// ---------------- launch -----------------
extern "C" void kernel_launch(void* const* d_in, const int* in_sizes, int n_in,
                              void* d_out, int out_size)
{
    const float* X  = (const float*)d_in[0];
    const float* Wq = (const float*)d_in[1];
    const float* bq = (const float*)d_in[2];
    const float* Wk = (const float*)d_in[3];
    const float* bk = (const float*)d_in[4];
    const float* Wv = (const float*)d_in[5];
    const float* bv = (const float*)d_in[6];
    const float* Wo = (const float*)d_in[7];
    const float* bo = (const float*)d_in[8];
    float* out = (float*)d_out;

    cudaFuncSetAttribute(attn_tc, cudaFuncAttributeMaxDynamicSharedMemorySize, ATT_SMEM);

    const int total4 = XTOT4 + 4 * WTOT4;
    cvt_all<<<(total4 + 255) / 256, 256>>>(X, Wq, Wk, Wv, Wo);
    gemm_qkv_h<<<dim3(D_ / 64, M_ / 128, 3), 256>>>(bq, bk, bv);
    vtail<<<24, 1024>>>();
    attn_tc<<<dim3(T_ / 64, B_ * H_), 256, ATT_SMEM>>>();
    gemm_out_h<<<dim3(D_ / 64, M_ / 128), 256>>>(bo, out);
}

// round 14
// speedup vs baseline: 1.2357x; 1.0118x over previous
#include <cuda_runtime.h>
#include <cuda_fp16.h>
#include <cstdint>

#define B_   2
#define T_   2048
#define D_   768
#define H_   12
#define DH_  64
#define M_   (B_ * T_)   // 4096

// softmax scale folded into Q: 0.125 * log2(e)
#define QSCALE 0.18033688011112042f

// ---------------- scratch (static device globals; no allocation) ----------------
__device__ half  g_Xh [M_ * D_];             // X in fp16
__device__ half  g_Wqh[D_ * D_];
__device__ half  g_Wkh[D_ * D_];
__device__ half  g_Wvh[D_ * D_];
__device__ half  g_Woh[D_ * D_];
__device__ half  g_Qh [B_ * H_ * T_ * DH_];  // [B,H,T,Dh] fp16 (pre-scaled)
__device__ half  g_Kh [B_ * H_ * T_ * DH_];
__device__ half  g_Vh [B_ * H_ * T_ * DH_];
__device__ half  g_AOh[M_ * D_];             // attention out, [B,T, H*Dh] fp16
__device__ float g_TS [24 * 33 * DH_];       // per-(bh,tile) V tile-suffix sums

// ---------------- helpers ----------------
#define MMA_F16(c, a, b)                                                         \
    asm volatile(                                                                \
        "mma.sync.aligned.m16n8k16.row.col.f32.f16.f16.f32 "                     \
        "{%0,%1,%2,%3},{%4,%5,%6,%7},{%8,%9},{%0,%1,%2,%3};"                     \
        : "+f"((c)[0]), "+f"((c)[1]), "+f"((c)[2]), "+f"((c)[3])                 \
        : "r"((a)[0]), "r"((a)[1]), "r"((a)[2]), "r"((a)[3]),                    \
          "r"((b)[0]), "r"((b)[1]))

__device__ __forceinline__ void ldmx4(uint32_t* r, uint32_t addr) {
    asm volatile("ldmatrix.sync.aligned.m8n8.x4.shared.b16 {%0,%1,%2,%3}, [%4];"
                 : "=r"(r[0]), "=r"(r[1]), "=r"(r[2]), "=r"(r[3]) : "r"(addr));
}
__device__ __forceinline__ void ldmx4t(uint32_t* r, uint32_t addr) {
    asm volatile("ldmatrix.sync.aligned.m8n8.x4.trans.shared.b16 {%0,%1,%2,%3}, [%4];"
                 : "=r"(r[0]), "=r"(r[1]), "=r"(r[2]), "=r"(r[3]) : "r"(addr));
}
__device__ __forceinline__ void ldmx2t(uint32_t* r, uint32_t addr) {
    asm volatile("ldmatrix.sync.aligned.m8n8.x2.trans.shared.b16 {%0,%1}, [%2];"
                 : "=r"(r[0]), "=r"(r[1]) : "r"(addr));
}
__device__ __forceinline__ uint32_t h2u(half2 h) { return *reinterpret_cast<uint32_t*>(&h); }

__device__ __forceinline__ void cpa16(uint32_t saddr, const void* g) {
    asm volatile("cp.async.cg.shared.global [%0], [%1], 16;" :: "r"(saddr), "l"(g));
}
__device__ __forceinline__ void cp_commit() { asm volatile("cp.async.commit_group;"); }
template <int N>
__device__ __forceinline__ void cp_wait() { asm volatile("cp.async.wait_group %0;" :: "n"(N)); }

// ---------------- fp32 -> fp16 conversion of X and the 4 weight matrices --------
#define XTOT4 (M_ * D_ / 4)     // 786432
#define WTOT4 (D_ * D_ / 4)     // 147456

__global__ __launch_bounds__(256)
void cvt_all(const float* __restrict__ X,
             const float* __restrict__ Wq, const float* __restrict__ Wk,
             const float* __restrict__ Wv, const float* __restrict__ Wo)
{
    int i = blockIdx.x * 256 + threadIdx.x;
    const int total = XTOT4 + 4 * WTOT4;
    if (i >= total) return;
    const float* src; half* dst; int off;
    if (i < XTOT4) { src = X; dst = g_Xh; off = i; }
    else {
        int j = i - XTOT4;
        int w = j / WTOT4;
        off = j - w * WTOT4;
        src = (w == 0) ? Wq : (w == 1) ? Wk : (w == 2) ? Wv : Wo;
        dst = (w == 0) ? g_Wqh : (w == 1) ? g_Wkh : (w == 2) ? g_Wvh : g_Woh;
    }
    float4 v = ((const float4*)src)[off];
    uint2 u = make_uint2(h2u(__floats2half2_rn(v.x, v.y)),
                         h2u(__floats2half2_rn(v.z, v.w)));
    ((uint2*)dst)[off] = u;
}

// ---------------- fp16 tensor-core GEMM mainloop (128x64 tile, k-chunk 64) ------
#define LDA 72

__device__ __forceinline__
void gemm_h_mainloop(const half* __restrict__ A, const half* __restrict__ W,
                     float c[2][4][4], half* As, half* Ws)
{
    const int tid  = threadIdx.x;
    const int lane = tid & 31;
    const int wid  = tid >> 5;
    const int wm   = wid & 3;
    const int wn   = wid >> 2;
    const int m0   = blockIdx.y * 128;
    const int n0   = blockIdx.x * 64;
    const int lrow = lane & 15;
    const int lcol = (lane >> 4) * 8;

#pragma unroll
    for (int mi = 0; mi < 2; mi++)
#pragma unroll
        for (int j = 0; j < 4; j++)
#pragma unroll
            for (int r = 0; r < 4; r++) c[mi][j][r] = 0.f;

    const uint32_t aaddr0 = (uint32_t)__cvta_generic_to_shared(
        &As[(wm * 32 + lrow) * LDA + lcol]);
    const uint32_t aaddr1 = aaddr0 + 16 * LDA * 2;
    const uint32_t baddr  = (uint32_t)__cvta_generic_to_shared(
        &Ws[lrow * LDA + wn * 32 + lcol]);

    for (int kk = 0; kk < D_; kk += 64) {
#pragma unroll
        for (int r = 0; r < 4; r++) {
            int idx = tid + r * 256;
            int row = idx >> 3;
            int c8  = (idx & 7) * 8;
            *(uint4*)&As[row * LDA + c8] =
                *(const uint4*)(A + (size_t)(m0 + row) * D_ + kk + c8);
        }
#pragma unroll
        for (int r = 0; r < 2; r++) {
            int idx = tid + r * 256;
            int row = idx >> 3;
            int c8  = (idx & 7) * 8;
            *(uint4*)&Ws[row * LDA + c8] =
                *(const uint4*)(W + (size_t)(kk + row) * D_ + n0 + c8);
        }
        __syncthreads();

#pragma unroll
        for (int ks = 0; ks < 4; ks++) {
            uint32_t af[2][4];
            ldmx4(af[0], aaddr0 + ks * 32);
            ldmx4(af[1], aaddr1 + ks * 32);
#pragma unroll
            for (int ni = 0; ni < 2; ni++) {
                uint32_t bf[4];
                ldmx4t(bf, baddr + (ks * 16 * LDA + ni * 16) * 2);
                uint32_t b0[2] = { bf[0], bf[1] };
                uint32_t b1[2] = { bf[2], bf[3] };
                MMA_F16(c[0][ni * 2],     af[0], b0);
                MMA_F16(c[0][ni * 2 + 1], af[0], b1);
                MMA_F16(c[1][ni * 2],     af[1], b0);
                MMA_F16(c[1][ni * 2 + 1], af[1], b1);
            }
        }
        __syncthreads();
    }
}

// QKV projection: blockIdx.z selects matrix; epilogue scatters half into [B,H,T,Dh].
// Q is pre-scaled by QSCALE so attention can use exp2 directly.
__global__ __launch_bounds__(256)
void gemm_qkv_h(const float* __restrict__ bq, const float* __restrict__ bk,
                const float* __restrict__ bv)
{
    __shared__ half As[128 * LDA];
    __shared__ half Ws[64 * LDA];

    const int z = blockIdx.z;
    const half*  W  = (z == 0) ? g_Wqh : (z == 1) ? g_Wkh : g_Wvh;
    const float* bb = (z == 0) ? bq    : (z == 1) ? bk    : bv;
    half*        Cd = (z == 0) ? g_Qh  : (z == 1) ? g_Kh  : g_Vh;
    const float  sc = (z == 0) ? QSCALE : 1.f;

    float c[2][4][4];
    gemm_h_mainloop(g_Xh, W, c, As, Ws);

    const int lane = threadIdx.x & 31;
    const int wid  = threadIdx.x >> 5;
    const int wm   = wid & 3;
    const int wn   = wid >> 2;
    const int gr   = lane >> 2;
    const int gc   = lane & 3;
    const int m0   = blockIdx.y * 128;
    const int n0   = blockIdx.x * 64;

#pragma unroll
    for (int mi = 0; mi < 2; mi++) {
#pragma unroll
        for (int j = 0; j < 4; j++) {
            int col = n0 + wn * 32 + j * 8 + 2 * gc;
            float b0 = bb[col], b1 = bb[col + 1];
            int h  = col >> 6;
            int dh = col & 63;
#pragma unroll
            for (int hp = 0; hp < 2; hp++) {
                int row = m0 + wm * 32 + mi * 16 + gr + hp * 8;
                int bt  = row >> 11;
                int t   = row & (T_ - 1);
                half2 v = __floats2half2_rn((c[mi][j][hp * 2] + b0) * sc,
                                            (c[mi][j][hp * 2 + 1] + b1) * sc);
                *(half2*)&Cd[((size_t)(bt * H_ + h) * T_ + t) * DH_ + dh] = v;
            }
        }
    }
}

// Output projection: AO(half) @ Wo + bo -> fp32 out.
__global__ __launch_bounds__(256)
void gemm_out_h(const float* __restrict__ bo, float* __restrict__ out)
{
    __shared__ half As[128 * LDA];
    __shared__ half Ws[64 * LDA];

    float c[2][4][4];
    gemm_h_mainloop(g_AOh, g_Woh, c, As, Ws);

    const int lane = threadIdx.x & 31;
    const int wid  = threadIdx.x >> 5;
    const int wm   = wid & 3;
    const int wn   = wid >> 2;
    const int gr   = lane >> 2;
    const int gc   = lane & 3;
    const int m0   = blockIdx.y * 128;
    const int n0   = blockIdx.x * 64;

#pragma unroll
    for (int mi = 0; mi < 2; mi++) {
#pragma unroll
        for (int j = 0; j < 4; j++) {
            int col = n0 + wn * 32 + j * 8 + 2 * gc;
            float b0 = bo[col], b1 = bo[col + 1];
#pragma unroll
            for (int hp = 0; hp < 2; hp++) {
                int row = m0 + wm * 32 + mi * 16 + gr + hp * 8;
                *(float2*)&out[(size_t)row * D_ + col] =
                    make_float2(c[mi][j][hp * 2] + b0, c[mi][j][hp * 2 + 1] + b1);
            }
        }
    }
}

// ---------------- fused V tile totals + suffix scan ----------------
__global__ __launch_bounds__(1024)
void vtail()
{
    __shared__ float ctot[32][64];
    __shared__ float suf[33][64];
    const int bh  = blockIdx.x;
    const int tid = threadIdx.x;
    const int d   = tid & 63;
    const int y   = tid >> 6;              // 0..15
    const half* V = g_Vh + (size_t)bh * T_ * DH_ + d;

#pragma unroll
    for (int rep = 0; rep < 2; rep++) {
        const int tl = y + rep * 16;
        const half* Vp = V + (size_t)tl * 64 * DH_;
        float sum = 0.f;
#pragma unroll 16
        for (int t = 0; t < 64; t++)
            sum += __half2float(Vp[(size_t)t * DH_]);
        ctot[tl][d] = sum;
    }
    __syncthreads();

    if (y == 0) {
        float s = 0.f;
        suf[32][d] = 0.f;
#pragma unroll
        for (int t = 31; t >= 0; t--) {
            s += ctot[t][d];
            suf[t][d] = s;
        }
    }
    __syncthreads();

    float* TS = g_TS + (size_t)bh * 33 * DH_;
#pragma unroll
    for (int i = tid; i < 33 * 64; i += 1024)
        TS[i] = suf[i >> 6][i & 63];
}

// ---------------- fp16 tensor-core causal attention (zero-fill semantics) -------
// 8 warps = 4 (m16 q-row groups) x 2 (32-key halves). Diagonal tile peeled
// (scalar exp2f + mask->1); mainloop uses ex2.approx.f16x2 (one MUFU per pair).
// Rowsums computed by MMA against a ones-column (V cols 64-71 preset to 1.0).
// 3-stage cp.async ring, ONE barrier per iteration.
#define LDH 72
#define KV_SZ (64 * LDH)                        // halves per K or V stage
#define ATT_SMEM ((64 * LDH + 6 * KV_SZ) * 2 + 4 * 16 * 64 * 4 + 64 * 4)  // 81152 B

__global__ __launch_bounds__(256, 2)
void attn_tc()
{
    extern __shared__ __align__(16) uint8_t smraw[];
    half* Qh = (half*)smraw;                  // 64 x LDH
    half* Kh = Qh + 64 * LDH;                 // 3 stages
    half* Vh = Kh + 3 * KV_SZ;                // 3 stages
    float* redO = (float*)(Vh + 3 * KV_SZ);   // 4*16 x 64
    float* redS = redO + 4 * 16 * 64;

    const int tid  = threadIdx.x;
    const int lane = tid & 31;
    const int wid  = tid >> 5;
    const int wm   = wid & 3;
    const int wh   = wid >> 2;
    const int gr   = lane >> 2;
    const int gc   = lane & 3;
    const int lrow = lane & 15;
    const int lcol = (lane >> 4) * 8;

    const int bh = blockIdx.y;
    const int qt = gridDim.x - 1 - blockIdx.x;    // heavy tiles first
    const int q0 = qt * 64;

    const half* Qg = g_Qh + (size_t)bh * T_ * DH_;
    const half* Kg = g_Kh + (size_t)bh * T_ * DH_;
    const half* Vg = g_Vh + (size_t)bh * T_ * DH_;

    const uint32_t qsb = (uint32_t)__cvta_generic_to_shared(Qh);
    const uint32_t ksb = (uint32_t)__cvta_generic_to_shared(Kh);
    const uint32_t vsb = (uint32_t)__cvta_generic_to_shared(Vh);

    // per-thread tile-load coordinates (64 rows x 8 uint4-cols; 2 chunks/thread)
    const int c8    = (tid & 7) * 8;
    const int row_a = (tid + 0)   >> 3;
    const int row_b = (tid + 256) >> 3;

    // preset ones-column (V cols 64-71) in all 3 stages; cp.async never touches it
    if (tid < 192) {
        int st  = tid >> 6;
        int row = tid & 63;
        uint4 ones;
        ones.x = ones.y = ones.z = ones.w = 0x3C003C00u;   // half 1.0 x8
        *(uint4*)&Vh[st * KV_SZ + row * LDH + 64] = ones;
    }

    auto prefetch = [&](int kt, int st) {
        const uint32_t so = (uint32_t)st * (KV_SZ * 2);
        const size_t ga = (size_t)(kt * 64 + row_a) * DH_ + c8;
        const size_t gb = (size_t)(kt * 64 + row_b) * DH_ + c8;
        cpa16(ksb + so + (row_a * LDH + c8) * 2, Kg + ga);
        cpa16(ksb + so + (row_b * LDH + c8) * 2, Kg + gb);
        cpa16(vsb + so + (row_a * LDH + c8) * 2, Vg + ga);
        cpa16(vsb + so + (row_b * LDH + c8) * 2, Vg + gb);
        cp_commit();
    };

    // ---- group 0: Q tile + K/V stage 0; group 1: stage 1 (if needed) ----
    cpa16(qsb + (row_a * LDH + c8) * 2, Qg + (size_t)(q0 + row_a) * DH_ + c8);
    cpa16(qsb + (row_b * LDH + c8) * 2, Qg + (size_t)(q0 + row_b) * DH_ + c8);
    cpa16(ksb + (row_a * LDH + c8) * 2, Kg + (size_t)row_a * DH_ + c8);
    cpa16(ksb + (row_b * LDH + c8) * 2, Kg + (size_t)row_b * DH_ + c8);
    cpa16(vsb + (row_a * LDH + c8) * 2, Vg + (size_t)row_a * DH_ + c8);
    cpa16(vsb + (row_b * LDH + c8) * 2, Vg + (size_t)row_b * DH_ + c8);
    cp_commit();
    if (qt >= 1) prefetch(1, 1);

    float o[8][4];
#pragma unroll
    for (int ni = 0; ni < 8; ni++)
#pragma unroll
        for (int r = 0; r < 4; r++) o[ni][r] = 0.f;
    float osum[4] = { 0.f, 0.f, 0.f, 0.f };   // rowsums via ones-column MMA
    uint32_t qf[4][4];

    const uint32_t kaddr_l = (uint32_t)__cvta_generic_to_shared(
        &Kh[(wh * 32 + lrow) * LDH + lcol]);
    const uint32_t vaddr_l = (uint32_t)__cvta_generic_to_shared(
        &Vh[(wh * 32 + lrow) * LDH + lcol]);
    const uint32_t qaddr = qsb + ((wm * 16 + lrow) * LDH + lcol) * 2;

    // body: S -> exp2 -> PV (+rowsum MMA) for one 64-key tile in stage st
    auto body = [&](int kt, int st, bool diag) {
        const uint32_t kaddr0 = kaddr_l + (uint32_t)st * (KV_SZ * 2);
        const uint32_t kaddr1 = kaddr0 + 16 * LDH * 2;
        const uint32_t vaddr0 = vaddr_l + (uint32_t)st * (KV_SZ * 2);
        const uint32_t vaddr1 = vaddr0 + 16 * LDH * 2;

        float s[4][4];
#pragma unroll
        for (int j = 0; j < 4; j++)
#pragma unroll
            for (int r = 0; r < 4; r++) s[j][r] = 0.f;

#pragma unroll
        for (int ks = 0; ks < 4; ks++) {
            uint32_t r0[4], r1[4];
            ldmx4(r0, kaddr0 + ks * 32);
            ldmx4(r1, kaddr1 + ks * 32);
            uint32_t b0[2] = { r0[0], r0[2] };
            uint32_t b1[2] = { r0[1], r0[3] };
            uint32_t b2[2] = { r1[0], r1[2] };
            uint32_t b3[2] = { r1[1], r1[3] };
            MMA_F16(s[0], qf[ks], b0);
            MMA_F16(s[1], qf[ks], b1);
            MMA_F16(s[2], qf[ks], b2);
            MMA_F16(s[3], qf[ks], b3);
        }

        uint32_t pl[4], ph[4];
        if (!diag) {
            // fast path: pack s to half2, one MUFU per pair
#pragma unroll
            for (int j = 0; j < 4; j++) {
                uint32_t slo = h2u(__floats2half2_rn(s[j][0], s[j][1]));
                uint32_t shi = h2u(__floats2half2_rn(s[j][2], s[j][3]));
                asm("ex2.approx.f16x2 %0, %1;" : "=r"(pl[j]) : "r"(slo));
                asm("ex2.approx.f16x2 %0, %1;" : "=r"(ph[j]) : "r"(shi));
            }
        } else {
            const int row0 = q0 + wm * 16 + gr;
#pragma unroll
            for (int j = 0; j < 4; j++) {
                float p0 = exp2f(s[j][0]);
                float p1 = exp2f(s[j][1]);
                float p2 = exp2f(s[j][2]);
                float p3 = exp2f(s[j][3]);
                int colg = kt * 64 + wh * 32 + j * 8 + 2 * gc;
                if (colg     > row0)     p0 = 1.f;
                if (colg + 1 > row0)     p1 = 1.f;
                if (colg     > row0 + 8) p2 = 1.f;
                if (colg + 1 > row0 + 8) p3 = 1.f;
                pl[j] = h2u(__floats2half2_rn(p0, p1));
                ph[j] = h2u(__floats2half2_rn(p2, p3));
            }
        }

#pragma unroll
        for (int ks2 = 0; ks2 < 2; ks2++) {
            uint32_t a[4] = { pl[ks2 * 2], ph[ks2 * 2], pl[ks2 * 2 + 1], ph[ks2 * 2 + 1] };
            uint32_t vbase = (ks2 == 0) ? vaddr0 : vaddr1;
#pragma unroll
            for (int dg = 0; dg < 4; dg++) {
                uint32_t rv[4];
                ldmx4t(rv, vbase + dg * 32);
                uint32_t bA[2] = { rv[0], rv[1] };
                uint32_t bB[2] = { rv[2], rv[3] };
                MMA_F16(o[dg * 2],     a, bA);
                MMA_F16(o[dg * 2 + 1], a, bB);
            }
            // rowsum via ones-column (cols 64-71)
            uint32_t rv2[2];
            ldmx2t(rv2, vbase + (64 - lcol) * 2);
            uint32_t bO[2] = { rv2[0], rv2[1] };
            MMA_F16(osum, a, bO);
        }
    };

    // ---- main loop: mask-free tiles kt = 0 .. qt-1 ----
    int stg = 0;
    for (int kt = 0; kt < qt; kt++) {
        cp_wait<1>();          // stage kt ready (group kt+1 may be in flight)
        __syncthreads();       // all warps done with iteration kt-1
        int st2 = stg + 2; if (st2 >= 3) st2 -= 3;
        if (kt + 2 <= qt) prefetch(kt + 2, st2);
        if (kt == 0) {
#pragma unroll
            for (int ks = 0; ks < 4; ks++)
                ldmx4(qf[ks], qaddr + ks * 32);
        }
        body(kt, stg, false);
        stg = (stg == 2) ? 0 : stg + 1;
    }

    // ---- diagonal tile kt = qt (masked; masked entries -> 1.0) ----
    cp_wait<0>();
    __syncthreads();
    if (qt == 0) {
#pragma unroll
        for (int ks = 0; ks < 4; ks++)
            ldmx4(qf[ks], qaddr + ks * 32);
    }
    body(qt, stg, true);

    // ---- cross-wh combine (rowsums already in osum via MMA; no shuffles) ----
    __syncthreads();
    if (wh == 0) {
        if (gc == 0) {
            redS[wm * 16 + gr]     = osum[0];
            redS[wm * 16 + 8 + gr] = osum[2];
        }
#pragma unroll
        for (int ni = 0; ni < 8; ni++) {
            int c = ni * 8 + 2 * gc;
            *(float2*)&redO[(wm * 16 + gr) * 64 + c]     = make_float2(o[ni][0], o[ni][1]);
            *(float2*)&redO[(wm * 16 + 8 + gr) * 64 + c] = make_float2(o[ni][2], o[ni][3]);
        }
    }
    __syncthreads();

    if (wh == 1) {
        const int b = bh / H_;
        const int h = bh - b * H_;
        const float tailN = (float)(T_ - (qt + 1) * 64);
        const float* vt = g_TS + ((size_t)bh * 33 + (qt + 1)) * DH_;
#pragma unroll
        for (int half_ = 0; half_ < 2; half_++) {
            int rl = wm * 16 + gr + 8 * half_;
            int qi = q0 + rl;
            float own = (half_ == 0) ? osum[0] : osum[2];
            float denom = own + redS[rl] + tailN;
            float inv = 1.f / denom;
            half* dst = g_AOh + ((size_t)(b * T_ + qi)) * D_ + h * DH_;
#pragma unroll
            for (int ni = 0; ni < 8; ni++) {
                int c = ni * 8 + 2 * gc;
                float2 red = *(const float2*)&redO[rl * 64 + c];
                float2 vtv = *(const float2*)&vt[c];
                float v0 = (o[ni][half_ * 2 + 0] + red.x + vtv.x) * inv;
                float v1 = (o[ni][half_ * 2 + 1] + red.y + vtv.y) * inv;
                *(half2*)&dst[c] = __floats2half2_rn(v0, v1);
            }
        }
    }
}

// ---------------- launch -----------------
extern "C" void kernel_launch(void* const* d_in, const int* in_sizes, int n_in,
                              void* d_out, int out_size)
{
    const float* X  = (const float*)d_in[0];
    const float* Wq = (const float*)d_in[1];
    const float* bq = (const float*)d_in[2];
    const float* Wk = (const float*)d_in[3];
    const float* bk = (const float*)d_in[4];
    const float* Wv = (const float*)d_in[5];
    const float* bv = (const float*)d_in[6];
    const float* Wo = (const float*)d_in[7];
    const float* bo = (const float*)d_in[8];
    float* out = (float*)d_out;

    cudaFuncSetAttribute(attn_tc, cudaFuncAttributeMaxDynamicSharedMemorySize, ATT_SMEM);

    const int total4 = XTOT4 + 4 * WTOT4;
    cvt_all<<<(total4 + 255) / 256, 256>>>(X, Wq, Wk, Wv, Wo);
    gemm_qkv_h<<<dim3(D_ / 64, M_ / 128, 3), 256>>>(bq, bk, bv);
    vtail<<<24, 1024>>>();
    attn_tc<<<dim3(T_ / 64, B_ * H_), 256, ATT_SMEM>>>();
    gemm_out_h<<<dim3(D_ / 64, M_ / 128), 256>>>(bo, out);
}

// round 15
// speedup vs baseline: 1.2638x; 1.0227x over previous
#include <cuda_runtime.h>
#include <cuda_fp16.h>
#include <cstdint>

#define B_   2
#define T_   2048
#define D_   768
#define H_   12
#define DH_  64
#define M_   (B_ * T_)   // 4096

// softmax scale folded into Q: 0.125 * log2(e)
#define QSCALE 0.18033688011112042f

// ---------------- scratch (static device globals; no allocation) ----------------
__device__ half  g_Xh [M_ * D_];             // X in fp16
__device__ half  g_Wqh[D_ * D_];
__device__ half  g_Wkh[D_ * D_];
__device__ half  g_Wvh[D_ * D_];
__device__ half  g_Woh[D_ * D_];
__device__ half  g_Qh [B_ * H_ * T_ * DH_];  // [B,H,T,Dh] fp16 (pre-scaled)
__device__ half  g_Kh [B_ * H_ * T_ * DH_];
__device__ half  g_Vh [B_ * H_ * T_ * DH_];
__device__ half  g_AOh[M_ * D_];             // attention out, [B,T, H*Dh] fp16
__device__ float g_TS [24 * 33 * DH_];       // per-(bh,tile) V tile-suffix sums

// ---------------- helpers ----------------
#define MMA_F16(c, a, b)                                                         \
    asm volatile(                                                                \
        "mma.sync.aligned.m16n8k16.row.col.f32.f16.f16.f32 "                     \
        "{%0,%1,%2,%3},{%4,%5,%6,%7},{%8,%9},{%0,%1,%2,%3};"                     \
        : "+f"((c)[0]), "+f"((c)[1]), "+f"((c)[2]), "+f"((c)[3])                 \
        : "r"((a)[0]), "r"((a)[1]), "r"((a)[2]), "r"((a)[3]),                    \
          "r"((b)[0]), "r"((b)[1]))

__device__ __forceinline__ void ldmx4(uint32_t* r, uint32_t addr) {
    asm volatile("ldmatrix.sync.aligned.m8n8.x4.shared.b16 {%0,%1,%2,%3}, [%4];"
                 : "=r"(r[0]), "=r"(r[1]), "=r"(r[2]), "=r"(r[3]) : "r"(addr));
}
__device__ __forceinline__ void ldmx4t(uint32_t* r, uint32_t addr) {
    asm volatile("ldmatrix.sync.aligned.m8n8.x4.trans.shared.b16 {%0,%1,%2,%3}, [%4];"
                 : "=r"(r[0]), "=r"(r[1]), "=r"(r[2]), "=r"(r[3]) : "r"(addr));
}
__device__ __forceinline__ void ldmx2t(uint32_t* r, uint32_t addr) {
    asm volatile("ldmatrix.sync.aligned.m8n8.x2.trans.shared.b16 {%0,%1}, [%2];"
                 : "=r"(r[0]), "=r"(r[1]) : "r"(addr));
}
__device__ __forceinline__ uint32_t h2u(half2 h) { return *reinterpret_cast<uint32_t*>(&h); }

__device__ __forceinline__ void cpa16(uint32_t saddr, const void* g) {
    asm volatile("cp.async.cg.shared.global [%0], [%1], 16;" :: "r"(saddr), "l"(g));
}
__device__ __forceinline__ void cp_commit() { asm volatile("cp.async.commit_group;"); }
template <int N>
__device__ __forceinline__ void cp_wait() { asm volatile("cp.async.wait_group %0;" :: "n"(N)); }

// ---------------- fp32 -> fp16 conversion of X and the 4 weight matrices --------
#define XTOT4 (M_ * D_ / 4)     // 786432
#define WTOT4 (D_ * D_ / 4)     // 147456

__global__ __launch_bounds__(256)
void cvt_all(const float* __restrict__ X,
             const float* __restrict__ Wq, const float* __restrict__ Wk,
             const float* __restrict__ Wv, const float* __restrict__ Wo)
{
    int i = blockIdx.x * 256 + threadIdx.x;
    const int total = XTOT4 + 4 * WTOT4;
    if (i >= total) return;
    const float* src; half* dst; int off;
    if (i < XTOT4) { src = X; dst = g_Xh; off = i; }
    else {
        int j = i - XTOT4;
        int w = j / WTOT4;
        off = j - w * WTOT4;
        src = (w == 0) ? Wq : (w == 1) ? Wk : (w == 2) ? Wv : Wo;
        dst = (w == 0) ? g_Wqh : (w == 1) ? g_Wkh : (w == 2) ? g_Wvh : g_Woh;
    }
    float4 v = ((const float4*)src)[off];
    uint2 u = make_uint2(h2u(__floats2half2_rn(v.x, v.y)),
                         h2u(__floats2half2_rn(v.z, v.w)));
    ((uint2*)dst)[off] = u;
}

// ---------------- fp16 GEMM mainloop, cp.async double-buffered ------------------
#define LDA 72
#define GA_SZ (128 * LDA)            // halves per A stage
#define GW_SZ (64 * LDA)
#define GEMM_SMEM ((2 * GA_SZ + 2 * GW_SZ) * 2)   // bytes = 55296

__device__ __forceinline__
void gemm_h_mainloop(const half* __restrict__ A, const half* __restrict__ W,
                     float c[2][4][4], half* As, half* Ws)
{
    const int tid  = threadIdx.x;
    const int lane = tid & 31;
    const int wid  = tid >> 5;
    const int wm   = wid & 3;
    const int wn   = wid >> 2;
    const int m0   = blockIdx.y * 128;
    const int n0   = blockIdx.x * 64;
    const int lrow = lane & 15;
    const int lcol = (lane >> 4) * 8;

#pragma unroll
    for (int mi = 0; mi < 2; mi++)
#pragma unroll
        for (int j = 0; j < 4; j++)
#pragma unroll
            for (int r = 0; r < 4; r++) c[mi][j][r] = 0.f;

    const uint32_t asb = (uint32_t)__cvta_generic_to_shared(As);
    const uint32_t wsb = (uint32_t)__cvta_generic_to_shared(Ws);

    // per-thread load coordinates
    const int arow[4] = { (tid + 0) >> 3, (tid + 256) >> 3, (tid + 512) >> 3, (tid + 768) >> 3 };
    const int ac8     = (tid & 7) * 8;
    const int wrow[2] = { (tid + 0) >> 3, (tid + 256) >> 3 };

    // stage 0
    {
#pragma unroll
        for (int r = 0; r < 4; r++)
            cpa16(asb + (arow[r] * LDA + ac8) * 2, A + (size_t)(m0 + arow[r]) * D_ + ac8);
#pragma unroll
        for (int r = 0; r < 2; r++)
            cpa16(wsb + (wrow[r] * LDA + ac8) * 2, W + (size_t)wrow[r] * D_ + n0 + ac8);
        cp_commit();
    }

    const uint32_t aaddr_l = (uint32_t)__cvta_generic_to_shared(
        &As[(wm * 32 + lrow) * LDA + lcol]);
    const uint32_t baddr_l = (uint32_t)__cvta_generic_to_shared(
        &Ws[lrow * LDA + wn * 32 + lcol]);

    const int NIT = D_ / 64;   // 12
    for (int it = 0; it < NIT; it++) {
        if (it + 1 < NIT) {
            const int kk = (it + 1) * 64;
            const uint32_t ao = ((it + 1) & 1) * (GA_SZ * 2);
            const uint32_t wo = ((it + 1) & 1) * (GW_SZ * 2);
#pragma unroll
            for (int r = 0; r < 4; r++)
                cpa16(asb + ao + (arow[r] * LDA + ac8) * 2,
                      A + (size_t)(m0 + arow[r]) * D_ + kk + ac8);
#pragma unroll
            for (int r = 0; r < 2; r++)
                cpa16(wsb + wo + (wrow[r] * LDA + ac8) * 2,
                      W + (size_t)(kk + wrow[r]) * D_ + n0 + ac8);
            cp_commit();
            cp_wait<1>();
        } else {
            cp_wait<0>();
        }
        __syncthreads();

        const uint32_t aaddr0 = aaddr_l + (it & 1) * (GA_SZ * 2);
        const uint32_t aaddr1 = aaddr0 + 16 * LDA * 2;
        const uint32_t baddr  = baddr_l + (it & 1) * (GW_SZ * 2);

#pragma unroll
        for (int ks = 0; ks < 4; ks++) {
            uint32_t af[2][4];
            ldmx4(af[0], aaddr0 + ks * 32);
            ldmx4(af[1], aaddr1 + ks * 32);
#pragma unroll
            for (int ni = 0; ni < 2; ni++) {
                uint32_t bf[4];
                ldmx4t(bf, baddr + (ks * 16 * LDA + ni * 16) * 2);
                uint32_t b0[2] = { bf[0], bf[1] };
                uint32_t b1[2] = { bf[2], bf[3] };
                MMA_F16(c[0][ni * 2],     af[0], b0);
                MMA_F16(c[0][ni * 2 + 1], af[0], b1);
                MMA_F16(c[1][ni * 2],     af[1], b0);
                MMA_F16(c[1][ni * 2 + 1], af[1], b1);
            }
        }
        __syncthreads();
    }
}

// QKV projection: blockIdx.z selects matrix; epilogue scatters half into [B,H,T,Dh].
// Q is pre-scaled by QSCALE so attention can use exp2 directly.
__global__ __launch_bounds__(256, 2)
void gemm_qkv_h(const float* __restrict__ bq, const float* __restrict__ bk,
                const float* __restrict__ bv)
{
    extern __shared__ __align__(16) half gsm[];
    half* As = gsm;
    half* Ws = gsm + 2 * GA_SZ;

    const int z = blockIdx.z;
    const half*  W  = (z == 0) ? g_Wqh : (z == 1) ? g_Wkh : g_Wvh;
    const float* bb = (z == 0) ? bq    : (z == 1) ? bk    : bv;
    half*        Cd = (z == 0) ? g_Qh  : (z == 1) ? g_Kh  : g_Vh;
    const float  sc = (z == 0) ? QSCALE : 1.f;

    float c[2][4][4];
    gemm_h_mainloop(g_Xh, W, c, As, Ws);

    const int lane = threadIdx.x & 31;
    const int wid  = threadIdx.x >> 5;
    const int wm   = wid & 3;
    const int wn   = wid >> 2;
    const int gr   = lane >> 2;
    const int gc   = lane & 3;
    const int m0   = blockIdx.y * 128;
    const int n0   = blockIdx.x * 64;

#pragma unroll
    for (int mi = 0; mi < 2; mi++) {
#pragma unroll
        for (int j = 0; j < 4; j++) {
            int col = n0 + wn * 32 + j * 8 + 2 * gc;
            float b0 = bb[col], b1 = bb[col + 1];
            int h  = col >> 6;
            int dh = col & 63;
#pragma unroll
            for (int hp = 0; hp < 2; hp++) {
                int row = m0 + wm * 32 + mi * 16 + gr + hp * 8;
                int bt  = row >> 11;
                int t   = row & (T_ - 1);
                half2 v = __floats2half2_rn((c[mi][j][hp * 2] + b0) * sc,
                                            (c[mi][j][hp * 2 + 1] + b1) * sc);
                *(half2*)&Cd[((size_t)(bt * H_ + h) * T_ + t) * DH_ + dh] = v;
            }
        }
    }
}

// Output projection: AO(half) @ Wo + bo -> fp32 out.
__global__ __launch_bounds__(256, 2)
void gemm_out_h(const float* __restrict__ bo, float* __restrict__ out)
{
    extern __shared__ __align__(16) half gsm[];
    half* As = gsm;
    half* Ws = gsm + 2 * GA_SZ;

    float c[2][4][4];
    gemm_h_mainloop(g_AOh, g_Woh, c, As, Ws);

    const int lane = threadIdx.x & 31;
    const int wid  = threadIdx.x >> 5;
    const int wm   = wid & 3;
    const int wn   = wid >> 2;
    const int gr   = lane >> 2;
    const int gc   = lane & 3;
    const int m0   = blockIdx.y * 128;
    const int n0   = blockIdx.x * 64;

#pragma unroll
    for (int mi = 0; mi < 2; mi++) {
#pragma unroll
        for (int j = 0; j < 4; j++) {
            int col = n0 + wn * 32 + j * 8 + 2 * gc;
            float b0 = bo[col], b1 = bo[col + 1];
#pragma unroll
            for (int hp = 0; hp < 2; hp++) {
                int row = m0 + wm * 32 + mi * 16 + gr + hp * 8;
                *(float2*)&out[(size_t)row * D_ + col] =
                    make_float2(c[mi][j][hp * 2] + b0, c[mi][j][hp * 2 + 1] + b1);
            }
        }
    }
}

// ---------------- fused V tile totals + suffix scan ----------------
__global__ __launch_bounds__(1024)
void vtail()
{
    __shared__ float ctot[32][64];
    __shared__ float suf[33][64];
    const int bh  = blockIdx.x;
    const int tid = threadIdx.x;
    const int d   = tid & 63;
    const int y   = tid >> 6;              // 0..15
    const half* V = g_Vh + (size_t)bh * T_ * DH_ + d;

#pragma unroll
    for (int rep = 0; rep < 2; rep++) {
        const int tl = y + rep * 16;
        const half* Vp = V + (size_t)tl * 64 * DH_;
        float sum = 0.f;
#pragma unroll 16
        for (int t = 0; t < 64; t++)
            sum += __half2float(Vp[(size_t)t * DH_]);
        ctot[tl][d] = sum;
    }
    __syncthreads();

    if (y == 0) {
        float s = 0.f;
        suf[32][d] = 0.f;
#pragma unroll
        for (int t = 31; t >= 0; t--) {
            s += ctot[t][d];
            suf[t][d] = s;
        }
    }
    __syncthreads();

    float* TS = g_TS + (size_t)bh * 33 * DH_;
#pragma unroll
    for (int i = tid; i < 33 * 64; i += 1024)
        TS[i] = suf[i >> 6][i & 63];
}

// ---------------- fp16 tensor-core causal attention (zero-fill semantics) -------
// 8 warps = 4 (m16 q-row groups) x 2 (32-key halves). Diagonal tile peeled
// (scalar exp2f + mask->1); mainloop uses ex2.approx.f16x2 (one MUFU per pair).
// Rowsums computed by MMA against a ones-column (V cols 64-71 preset to 1.0).
// 3-stage cp.async ring, ONE barrier per iteration.  [round-14 best version]
#define LDH 72
#define KV_SZ (64 * LDH)                        // halves per K or V stage
#define ATT_SMEM ((64 * LDH + 6 * KV_SZ) * 2 + 4 * 16 * 64 * 4 + 64 * 4)  // 81152 B

__global__ __launch_bounds__(256, 2)
void attn_tc()
{
    extern __shared__ __align__(16) uint8_t smraw[];
    half* Qh = (half*)smraw;                  // 64 x LDH
    half* Kh = Qh + 64 * LDH;                 // 3 stages
    half* Vh = Kh + 3 * KV_SZ;                // 3 stages
    float* redO = (float*)(Vh + 3 * KV_SZ);   // 4*16 x 64
    float* redS = redO + 4 * 16 * 64;

    const int tid  = threadIdx.x;
    const int lane = tid & 31;
    const int wid  = tid >> 5;
    const int wm   = wid & 3;
    const int wh   = wid >> 2;
    const int gr   = lane >> 2;
    const int gc   = lane & 3;
    const int lrow = lane & 15;
    const int lcol = (lane >> 4) * 8;

    const int bh = blockIdx.y;
    const int qt = gridDim.x - 1 - blockIdx.x;    // heavy tiles first
    const int q0 = qt * 64;

    const half* Qg = g_Qh + (size_t)bh * T_ * DH_;
    const half* Kg = g_Kh + (size_t)bh * T_ * DH_;
    const half* Vg = g_Vh + (size_t)bh * T_ * DH_;

    const uint32_t qsb = (uint32_t)__cvta_generic_to_shared(Qh);
    const uint32_t ksb = (uint32_t)__cvta_generic_to_shared(Kh);
    const uint32_t vsb = (uint32_t)__cvta_generic_to_shared(Vh);

    // per-thread tile-load coordinates (64 rows x 8 uint4-cols; 2 chunks/thread)
    const int c8    = (tid & 7) * 8;
    const int row_a = (tid + 0)   >> 3;
    const int row_b = (tid + 256) >> 3;

    // preset ones-column (V cols 64-71) in all 3 stages; cp.async never touches it
    if (tid < 192) {
        int st  = tid >> 6;
        int row = tid & 63;
        uint4 ones;
        ones.x = ones.y = ones.z = ones.w = 0x3C003C00u;   // half 1.0 x8
        *(uint4*)&Vh[st * KV_SZ + row * LDH + 64] = ones;
    }

    auto prefetch = [&](int kt, int st) {
        const uint32_t so = (uint32_t)st * (KV_SZ * 2);
        const size_t ga = (size_t)(kt * 64 + row_a) * DH_ + c8;
        const size_t gb = (size_t)(kt * 64 + row_b) * DH_ + c8;
        cpa16(ksb + so + (row_a * LDH + c8) * 2, Kg + ga);
        cpa16(ksb + so + (row_b * LDH + c8) * 2, Kg + gb);
        cpa16(vsb + so + (row_a * LDH + c8) * 2, Vg + ga);
        cpa16(vsb + so + (row_b * LDH + c8) * 2, Vg + gb);
        cp_commit();
    };

    // ---- group 0: Q tile + K/V stage 0; group 1: stage 1 (if needed) ----
    cpa16(qsb + (row_a * LDH + c8) * 2, Qg + (size_t)(q0 + row_a) * DH_ + c8);
    cpa16(qsb + (row_b * LDH + c8) * 2, Qg + (size_t)(q0 + row_b) * DH_ + c8);
    cpa16(ksb + (row_a * LDH + c8) * 2, Kg + (size_t)row_a * DH_ + c8);
    cpa16(ksb + (row_b * LDH + c8) * 2, Kg + (size_t)row_b * DH_ + c8);
    cpa16(vsb + (row_a * LDH + c8) * 2, Vg + (size_t)row_a * DH_ + c8);
    cpa16(vsb + (row_b * LDH + c8) * 2, Vg + (size_t)row_b * DH_ + c8);
    cp_commit();
    if (qt >= 1) prefetch(1, 1);

    float o[8][4];
#pragma unroll
    for (int ni = 0; ni < 8; ni++)
#pragma unroll
        for (int r = 0; r < 4; r++) o[ni][r] = 0.f;
    float osum[4] = { 0.f, 0.f, 0.f, 0.f };   // rowsums via ones-column MMA
    uint32_t qf[4][4];

    const uint32_t kaddr_l = (uint32_t)__cvta_generic_to_shared(
        &Kh[(wh * 32 + lrow) * LDH + lcol]);
    const uint32_t vaddr_l = (uint32_t)__cvta_generic_to_shared(
        &Vh[(wh * 32 + lrow) * LDH + lcol]);
    const uint32_t qaddr = qsb + ((wm * 16 + lrow) * LDH + lcol) * 2;

    // body: S -> exp2 -> PV (+rowsum MMA) for one 64-key tile in stage st
    auto body = [&](int kt, int st, bool diag) {
        const uint32_t kaddr0 = kaddr_l + (uint32_t)st * (KV_SZ * 2);
        const uint32_t kaddr1 = kaddr0 + 16 * LDH * 2;
        const uint32_t vaddr0 = vaddr_l + (uint32_t)st * (KV_SZ * 2);
        const uint32_t vaddr1 = vaddr0 + 16 * LDH * 2;

        float s[4][4];
#pragma unroll
        for (int j = 0; j < 4; j++)
#pragma unroll
            for (int r = 0; r < 4; r++) s[j][r] = 0.f;

#pragma unroll
        for (int ks = 0; ks < 4; ks++) {
            uint32_t r0[4], r1[4];
            ldmx4(r0, kaddr0 + ks * 32);
            ldmx4(r1, kaddr1 + ks * 32);
            uint32_t b0[2] = { r0[0], r0[2] };
            uint32_t b1[2] = { r0[1], r0[3] };
            uint32_t b2[2] = { r1[0], r1[2] };
            uint32_t b3[2] = { r1[1], r1[3] };
            MMA_F16(s[0], qf[ks], b0);
            MMA_F16(s[1], qf[ks], b1);
            MMA_F16(s[2], qf[ks], b2);
            MMA_F16(s[3], qf[ks], b3);
        }

        uint32_t pl[4], ph[4];
        if (!diag) {
            // fast path: pack s to half2, one MUFU per pair
#pragma unroll
            for (int j = 0; j < 4; j++) {
                uint32_t slo = h2u(__floats2half2_rn(s[j][0], s[j][1]));
                uint32_t shi = h2u(__floats2half2_rn(s[j][2], s[j][3]));
                asm("ex2.approx.f16x2 %0, %1;" : "=r"(pl[j]) : "r"(slo));
                asm("ex2.approx.f16x2 %0, %1;" : "=r"(ph[j]) : "r"(shi));
            }
        } else {
            const int row0 = q0 + wm * 16 + gr;
#pragma unroll
            for (int j = 0; j < 4; j++) {
                float p0 = exp2f(s[j][0]);
                float p1 = exp2f(s[j][1]);
                float p2 = exp2f(s[j][2]);
                float p3 = exp2f(s[j][3]);
                int colg = kt * 64 + wh * 32 + j * 8 + 2 * gc;
                if (colg     > row0)     p0 = 1.f;
                if (colg + 1 > row0)     p1 = 1.f;
                if (colg     > row0 + 8) p2 = 1.f;
                if (colg + 1 > row0 + 8) p3 = 1.f;
                pl[j] = h2u(__floats2half2_rn(p0, p1));
                ph[j] = h2u(__floats2half2_rn(p2, p3));
            }
        }

#pragma unroll
        for (int ks2 = 0; ks2 < 2; ks2++) {
            uint32_t a[4] = { pl[ks2 * 2], ph[ks2 * 2], pl[ks2 * 2 + 1], ph[ks2 * 2 + 1] };
            uint32_t vbase = (ks2 == 0) ? vaddr0 : vaddr1;
#pragma unroll
            for (int dg = 0; dg < 4; dg++) {
                uint32_t rv[4];
                ldmx4t(rv, vbase + dg * 32);
                uint32_t bA[2] = { rv[0], rv[1] };
                uint32_t bB[2] = { rv[2], rv[3] };
                MMA_F16(o[dg * 2],     a, bA);
                MMA_F16(o[dg * 2 + 1], a, bB);
            }
            // rowsum via ones-column (cols 64-71)
            uint32_t rv2[2];
            ldmx2t(rv2, vbase + (64 - lcol) * 2);
            uint32_t bO[2] = { rv2[0], rv2[1] };
            MMA_F16(osum, a, bO);
        }
    };

    // ---- main loop: mask-free tiles kt = 0 .. qt-1 ----
    int stg = 0;
    for (int kt = 0; kt < qt; kt++) {
        cp_wait<1>();          // stage kt ready (group kt+1 may be in flight)
        __syncthreads();       // all warps done with iteration kt-1
        int st2 = stg + 2; if (st2 >= 3) st2 -= 3;
        if (kt + 2 <= qt) prefetch(kt + 2, st2);
        if (kt == 0) {
#pragma unroll
            for (int ks = 0; ks < 4; ks++)
                ldmx4(qf[ks], qaddr + ks * 32);
        }
        body(kt, stg, false);
        stg = (stg == 2) ? 0 : stg + 1;
    }

    // ---- diagonal tile kt = qt (masked; masked entries -> 1.0) ----
    cp_wait<0>();
    __syncthreads();
    if (qt == 0) {
#pragma unroll
        for (int ks = 0; ks < 4; ks++)
            ldmx4(qf[ks], qaddr + ks * 32);
    }
    body(qt, stg, true);

    // ---- cross-wh combine (rowsums already in osum via MMA; no shuffles) ----
    __syncthreads();
    if (wh == 0) {
        if (gc == 0) {
            redS[wm * 16 + gr]     = osum[0];
            redS[wm * 16 + 8 + gr] = osum[2];
        }
#pragma unroll
        for (int ni = 0; ni < 8; ni++) {
            int c = ni * 8 + 2 * gc;
            *(float2*)&redO[(wm * 16 + gr) * 64 + c]     = make_float2(o[ni][0], o[ni][1]);
            *(float2*)&redO[(wm * 16 + 8 + gr) * 64 + c] = make_float2(o[ni][2], o[ni][3]);
        }
    }
    __syncthreads();

    if (wh == 1) {
        const int b = bh / H_;
        const int h = bh - b * H_;
        const float tailN = (float)(T_ - (qt + 1) * 64);
        const float* vt = g_TS + ((size_t)bh * 33 + (qt + 1)) * DH_;
#pragma unroll
        for (int half_ = 0; half_ < 2; half_++) {
            int rl = wm * 16 + gr + 8 * half_;
            int qi = q0 + rl;
            float own = (half_ == 0) ? osum[0] : osum[2];
            float denom = own + redS[rl] + tailN;
            float inv = 1.f / denom;
            half* dst = g_AOh + ((size_t)(b * T_ + qi)) * D_ + h * DH_;
#pragma unroll
            for (int ni = 0; ni < 8; ni++) {
                int c = ni * 8 + 2 * gc;
                float2 red = *(const float2*)&redO[rl * 64 + c];
                float2 vtv = *(const float2*)&vt[c];
                float v0 = (o[ni][half_ * 2 + 0] + red.x + vtv.x) * inv;
                float v1 = (o[ni][half_ * 2 + 1] + red.y + vtv.y) * inv;
                *(half2*)&dst[c] = __floats2half2_rn(v0, v1);
            }
        }
    }
}

// ---------------- launch -----------------
extern "C" void kernel_launch(void* const* d_in, const int* in_sizes, int n_in,
                              void* d_out, int out_size)
{
    const float* X  = (const float*)d_in[0];
    const float* Wq = (const float*)d_in[1];
    const float* bq = (const float*)d_in[2];
    const float* Wk = (const float*)d_in[3];
    const float* bk = (const float*)d_in[4];
    const float* Wv = (const float*)d_in[5];
    const float* bv = (const float*)d_in[6];
    const float* Wo = (const float*)d_in[7];
    const float* bo = (const float*)d_in[8];
    float* out = (float*)d_out;

    cudaFuncSetAttribute(attn_tc,    cudaFuncAttributeMaxDynamicSharedMemorySize, ATT_SMEM);
    cudaFuncSetAttribute(gemm_qkv_h, cudaFuncAttributeMaxDynamicSharedMemorySize, GEMM_SMEM);
    cudaFuncSetAttribute(gemm_out_h, cudaFuncAttributeMaxDynamicSharedMemorySize, GEMM_SMEM);

    const int total4 = XTOT4 + 4 * WTOT4;
    cvt_all<<<(total4 + 255) / 256, 256>>>(X, Wq, Wk, Wv, Wo);
    gemm_qkv_h<<<dim3(D_ / 64, M_ / 128, 3), 256, GEMM_SMEM>>>(bq, bk, bv);
    vtail<<<24, 1024>>>();
    attn_tc<<<dim3(T_ / 64, B_ * H_), 256, ATT_SMEM>>>();
    gemm_out_h<<<dim3(D_ / 64, M_ / 128), 256, GEMM_SMEM>>>(bo, out);
}

// round 16
// speedup vs baseline: 1.3610x; 1.0769x over previous
#include <cuda_runtime.h>
#include <cuda_fp16.h>
#include <cstdint>

#define B_   2
#define T_   2048
#define D_   768
#define H_   12
#define DH_  64
#define M_   (B_ * T_)   // 4096

// softmax scale folded into Q: 0.125 * log2(e)
#define QSCALE 0.18033688011112042f

// ---------------- scratch (static device globals; no allocation) ----------------
__device__ half  g_Xh [M_ * D_];             // X in fp16
__device__ half  g_Wqh[D_ * D_];
__device__ half  g_Wkh[D_ * D_];
__device__ half  g_Wvh[D_ * D_];
__device__ half  g_Woh[D_ * D_];
__device__ half  g_Qh [B_ * H_ * T_ * DH_];  // [B,H,T,Dh] fp16 (pre-scaled)
__device__ half  g_Kh [B_ * H_ * T_ * DH_];
__device__ half  g_Vh [B_ * H_ * T_ * DH_];
__device__ half  g_AOh[M_ * D_];             // attention out, [B,T, H*Dh] fp16
__device__ float g_TS [24 * 33 * DH_];       // per-(bh,tile) V tile-suffix sums

// ---------------- helpers ----------------
#define MMA_F16(c, a, b)                                                         \
    asm volatile(                                                                \
        "mma.sync.aligned.m16n8k16.row.col.f32.f16.f16.f32 "                     \
        "{%0,%1,%2,%3},{%4,%5,%6,%7},{%8,%9},{%0,%1,%2,%3};"                     \
        : "+f"((c)[0]), "+f"((c)[1]), "+f"((c)[2]), "+f"((c)[3])                 \
        : "r"((a)[0]), "r"((a)[1]), "r"((a)[2]), "r"((a)[3]),                    \
          "r"((b)[0]), "r"((b)[1]))

__device__ __forceinline__ void ldmx4(uint32_t* r, uint32_t addr) {
    asm volatile("ldmatrix.sync.aligned.m8n8.x4.shared.b16 {%0,%1,%2,%3}, [%4];"
                 : "=r"(r[0]), "=r"(r[1]), "=r"(r[2]), "=r"(r[3]) : "r"(addr));
}
__device__ __forceinline__ void ldmx4t(uint32_t* r, uint32_t addr) {
    asm volatile("ldmatrix.sync.aligned.m8n8.x4.trans.shared.b16 {%0,%1,%2,%3}, [%4];"
                 : "=r"(r[0]), "=r"(r[1]), "=r"(r[2]), "=r"(r[3]) : "r"(addr));
}
__device__ __forceinline__ void ldmx2t(uint32_t* r, uint32_t addr) {
    asm volatile("ldmatrix.sync.aligned.m8n8.x2.trans.shared.b16 {%0,%1}, [%2];"
                 : "=r"(r[0]), "=r"(r[1]) : "r"(addr));
}
__device__ __forceinline__ uint32_t h2u(half2 h) { return *reinterpret_cast<uint32_t*>(&h); }

__device__ __forceinline__ void cpa16(uint32_t saddr, const void* g) {
    asm volatile("cp.async.cg.shared.global [%0], [%1], 16;" :: "r"(saddr), "l"(g));
}
__device__ __forceinline__ void cp_commit() { asm volatile("cp.async.commit_group;"); }
template <int N>
__device__ __forceinline__ void cp_wait() { asm volatile("cp.async.wait_group %0;" :: "n"(N)); }

// ---------------- fp32 -> fp16 conversion of X and the 4 weight matrices --------
#define XTOT4 (M_ * D_ / 4)     // 786432
#define WTOT4 (D_ * D_ / 4)     // 147456

__global__ __launch_bounds__(256)
void cvt_all(const float* __restrict__ X,
             const float* __restrict__ Wq, const float* __restrict__ Wk,
             const float* __restrict__ Wv, const float* __restrict__ Wo)
{
    int i = blockIdx.x * 256 + threadIdx.x;
    const int total = XTOT4 + 4 * WTOT4;
    if (i >= total) return;
    const float* src; half* dst; int off;
    if (i < XTOT4) { src = X; dst = g_Xh; off = i; }
    else {
        int j = i - XTOT4;
        int w = j / WTOT4;
        off = j - w * WTOT4;
        src = (w == 0) ? Wq : (w == 1) ? Wk : (w == 2) ? Wv : Wo;
        dst = (w == 0) ? g_Wqh : (w == 1) ? g_Wkh : (w == 2) ? g_Wvh : g_Woh;
    }
    float4 v = ((const float4*)src)[off];
    uint2 u = make_uint2(h2u(__floats2half2_rn(v.x, v.y)),
                         h2u(__floats2half2_rn(v.z, v.w)));
    ((uint2*)dst)[off] = u;
}

// ---------------- fp16 GEMM mainloop, 128x128 tile, cp.async double-buffered ----
// 8 warps = 4(m) x 2(n); warp tile 32(m) x 64(n); k-chunk 64.
#define LDA 72                        // A stage row stride (halves)
#define LDW 136                       // W stage row stride (halves): 272B = 4-bank stagger
#define GA_SZ (128 * LDA)             // halves per A stage
#define GW_SZ (64 * LDW)              // halves per W stage
#define GEMM_SMEM ((2 * GA_SZ + 2 * GW_SZ) * 2)   // 71680 B

__device__ __forceinline__
void gemm_h_mainloop(const half* __restrict__ A, const half* __restrict__ W,
                     float c[2][8][4], half* As, half* Ws)
{
    const int tid  = threadIdx.x;
    const int lane = tid & 31;
    const int wid  = tid >> 5;
    const int wm   = wid & 3;
    const int wn   = wid >> 2;
    const int m0   = blockIdx.y * 128;
    const int n0   = blockIdx.x * 128;
    const int lrow = lane & 15;
    const int lcol = (lane >> 4) * 8;

#pragma unroll
    for (int mi = 0; mi < 2; mi++)
#pragma unroll
        for (int j = 0; j < 8; j++)
#pragma unroll
            for (int r = 0; r < 4; r++) c[mi][j][r] = 0.f;

    const uint32_t asb = (uint32_t)__cvta_generic_to_shared(As);
    const uint32_t wsb = (uint32_t)__cvta_generic_to_shared(Ws);

    // per-thread load coordinates
    const int arow[4] = { (tid + 0) >> 3, (tid + 256) >> 3, (tid + 512) >> 3, (tid + 768) >> 3 };
    const int ac8     = (tid & 7) * 8;
    const int wrow[4] = { (tid + 0) >> 4, (tid + 256) >> 4, (tid + 512) >> 4, (tid + 768) >> 4 };
    const int wc8     = (tid & 15) * 8;

    // stage 0
    {
#pragma unroll
        for (int r = 0; r < 4; r++)
            cpa16(asb + (arow[r] * LDA + ac8) * 2, A + (size_t)(m0 + arow[r]) * D_ + ac8);
#pragma unroll
        for (int r = 0; r < 4; r++)
            cpa16(wsb + (wrow[r] * LDW + wc8) * 2, W + (size_t)wrow[r] * D_ + n0 + wc8);
        cp_commit();
    }

    const uint32_t aaddr_l = (uint32_t)__cvta_generic_to_shared(
        &As[(wm * 32 + lrow) * LDA + lcol]);
    const uint32_t baddr_l = (uint32_t)__cvta_generic_to_shared(
        &Ws[lrow * LDW + wn * 64 + lcol]);

    const int NIT = D_ / 64;   // 12
    for (int it = 0; it < NIT; it++) {
        if (it + 1 < NIT) {
            const int kk = (it + 1) * 64;
            const uint32_t ao = ((it + 1) & 1) * (GA_SZ * 2);
            const uint32_t wo = ((it + 1) & 1) * (GW_SZ * 2);
#pragma unroll
            for (int r = 0; r < 4; r++)
                cpa16(asb + ao + (arow[r] * LDA + ac8) * 2,
                      A + (size_t)(m0 + arow[r]) * D_ + kk + ac8);
#pragma unroll
            for (int r = 0; r < 4; r++)
                cpa16(wsb + wo + (wrow[r] * LDW + wc8) * 2,
                      W + (size_t)(kk + wrow[r]) * D_ + n0 + wc8);
            cp_commit();
            cp_wait<1>();
        } else {
            cp_wait<0>();
        }
        __syncthreads();

        const uint32_t aaddr0 = aaddr_l + (it & 1) * (GA_SZ * 2);
        const uint32_t aaddr1 = aaddr0 + 16 * LDA * 2;
        const uint32_t baddr  = baddr_l + (it & 1) * (GW_SZ * 2);

#pragma unroll
        for (int ks = 0; ks < 4; ks++) {
            uint32_t af[2][4];
            ldmx4(af[0], aaddr0 + ks * 32);
            ldmx4(af[1], aaddr1 + ks * 32);
#pragma unroll
            for (int ni = 0; ni < 4; ni++) {
                uint32_t bf[4];
                ldmx4t(bf, baddr + (ks * 16 * LDW + ni * 16) * 2);
                uint32_t b0[2] = { bf[0], bf[1] };
                uint32_t b1[2] = { bf[2], bf[3] };
                MMA_F16(c[0][ni * 2],     af[0], b0);
                MMA_F16(c[0][ni * 2 + 1], af[0], b1);
                MMA_F16(c[1][ni * 2],     af[1], b0);
                MMA_F16(c[1][ni * 2 + 1], af[1], b1);
            }
        }
        __syncthreads();
    }
}

// QKV projection: blockIdx.z selects matrix; epilogue scatters half into [B,H,T,Dh].
// Q is pre-scaled by QSCALE so attention can use exp2 directly.
__global__ __launch_bounds__(256, 2)
void gemm_qkv_h(const float* __restrict__ bq, const float* __restrict__ bk,
                const float* __restrict__ bv)
{
    extern __shared__ __align__(16) half gsm[];
    half* As = gsm;
    half* Ws = gsm + 2 * GA_SZ;

    const int z = blockIdx.z;
    const half*  W  = (z == 0) ? g_Wqh : (z == 1) ? g_Wkh : g_Wvh;
    const float* bb = (z == 0) ? bq    : (z == 1) ? bk    : bv;
    half*        Cd = (z == 0) ? g_Qh  : (z == 1) ? g_Kh  : g_Vh;
    const float  sc = (z == 0) ? QSCALE : 1.f;

    float c[2][8][4];
    gemm_h_mainloop(g_Xh, W, c, As, Ws);

    const int lane = threadIdx.x & 31;
    const int wid  = threadIdx.x >> 5;
    const int wm   = wid & 3;
    const int wn   = wid >> 2;
    const int gr   = lane >> 2;
    const int gc   = lane & 3;
    const int m0   = blockIdx.y * 128;
    const int n0   = blockIdx.x * 128;

#pragma unroll
    for (int mi = 0; mi < 2; mi++) {
#pragma unroll
        for (int j = 0; j < 8; j++) {
            int col = n0 + wn * 64 + j * 8 + 2 * gc;
            float b0 = bb[col], b1 = bb[col + 1];
            int h  = col >> 6;
            int dh = col & 63;
#pragma unroll
            for (int hp = 0; hp < 2; hp++) {
                int row = m0 + wm * 32 + mi * 16 + gr + hp * 8;
                int bt  = row >> 11;
                int t   = row & (T_ - 1);
                half2 v = __floats2half2_rn((c[mi][j][hp * 2] + b0) * sc,
                                            (c[mi][j][hp * 2 + 1] + b1) * sc);
                *(half2*)&Cd[((size_t)(bt * H_ + h) * T_ + t) * DH_ + dh] = v;
            }
        }
    }
}

// Output projection: AO(half) @ Wo + bo -> fp32 out.
__global__ __launch_bounds__(256, 2)
void gemm_out_h(const float* __restrict__ bo, float* __restrict__ out)
{
    extern __shared__ __align__(16) half gsm[];
    half* As = gsm;
    half* Ws = gsm + 2 * GA_SZ;

    float c[2][8][4];
    gemm_h_mainloop(g_AOh, g_Woh, c, As, Ws);

    const int lane = threadIdx.x & 31;
    const int wid  = threadIdx.x >> 5;
    const int wm   = wid & 3;
    const int wn   = wid >> 2;
    const int gr   = lane >> 2;
    const int gc   = lane & 3;
    const int m0   = blockIdx.y * 128;
    const int n0   = blockIdx.x * 128;

#pragma unroll
    for (int mi = 0; mi < 2; mi++) {
#pragma unroll
        for (int j = 0; j < 8; j++) {
            int col = n0 + wn * 64 + j * 8 + 2 * gc;
            float b0 = bo[col], b1 = bo[col + 1];
#pragma unroll
            for (int hp = 0; hp < 2; hp++) {
                int row = m0 + wm * 32 + mi * 16 + gr + hp * 8;
                *(float2*)&out[(size_t)row * D_ + col] =
                    make_float2(c[mi][j][hp * 2] + b0, c[mi][j][hp * 2 + 1] + b1);
            }
        }
    }
}

// ---------------- fused V tile totals + suffix scan ----------------
__global__ __launch_bounds__(1024)
void vtail()
{
    __shared__ float ctot[32][64];
    __shared__ float suf[33][64];
    const int bh  = blockIdx.x;
    const int tid = threadIdx.x;
    const int d   = tid & 63;
    const int y   = tid >> 6;              // 0..15
    const half* V = g_Vh + (size_t)bh * T_ * DH_ + d;

#pragma unroll
    for (int rep = 0; rep < 2; rep++) {
        const int tl = y + rep * 16;
        const half* Vp = V + (size_t)tl * 64 * DH_;
        float sum = 0.f;
#pragma unroll 16
        for (int t = 0; t < 64; t++)
            sum += __half2float(Vp[(size_t)t * DH_]);
        ctot[tl][d] = sum;
    }
    __syncthreads();

    if (y == 0) {
        float s = 0.f;
        suf[32][d] = 0.f;
#pragma unroll
        for (int t = 31; t >= 0; t--) {
            s += ctot[t][d];
            suf[t][d] = s;
        }
    }
    __syncthreads();

    float* TS = g_TS + (size_t)bh * 33 * DH_;
#pragma unroll
    for (int i = tid; i < 33 * 64; i += 1024)
        TS[i] = suf[i >> 6][i & 63];
}

// ---------------- fp16 tensor-core causal attention (zero-fill semantics) -------
// [round-15 best version — unchanged]
#define LDH 72
#define KV_SZ (64 * LDH)                        // halves per K or V stage
#define ATT_SMEM ((64 * LDH + 6 * KV_SZ) * 2 + 4 * 16 * 64 * 4 + 64 * 4)  // 81152 B

__global__ __launch_bounds__(256, 2)
void attn_tc()
{
    extern __shared__ __align__(16) uint8_t smraw[];
    half* Qh = (half*)smraw;                  // 64 x LDH
    half* Kh = Qh + 64 * LDH;                 // 3 stages
    half* Vh = Kh + 3 * KV_SZ;                // 3 stages
    float* redO = (float*)(Vh + 3 * KV_SZ);   // 4*16 x 64
    float* redS = redO + 4 * 16 * 64;

    const int tid  = threadIdx.x;
    const int lane = tid & 31;
    const int wid  = tid >> 5;
    const int wm   = wid & 3;
    const int wh   = wid >> 2;
    const int gr   = lane >> 2;
    const int gc   = lane & 3;
    const int lrow = lane & 15;
    const int lcol = (lane >> 4) * 8;

    const int bh = blockIdx.y;
    const int qt = gridDim.x - 1 - blockIdx.x;    // heavy tiles first
    const int q0 = qt * 64;

    const half* Qg = g_Qh + (size_t)bh * T_ * DH_;
    const half* Kg = g_Kh + (size_t)bh * T_ * DH_;
    const half* Vg = g_Vh + (size_t)bh * T_ * DH_;

    const uint32_t qsb = (uint32_t)__cvta_generic_to_shared(Qh);
    const uint32_t ksb = (uint32_t)__cvta_generic_to_shared(Kh);
    const uint32_t vsb = (uint32_t)__cvta_generic_to_shared(Vh);

    const int c8    = (tid & 7) * 8;
    const int row_a = (tid + 0)   >> 3;
    const int row_b = (tid + 256) >> 3;

    // preset ones-column (V cols 64-71) in all 3 stages; cp.async never touches it
    if (tid < 192) {
        int st  = tid >> 6;
        int row = tid & 63;
        uint4 ones;
        ones.x = ones.y = ones.z = ones.w = 0x3C003C00u;   // half 1.0 x8
        *(uint4*)&Vh[st * KV_SZ + row * LDH + 64] = ones;
    }

    auto prefetch = [&](int kt, int st) {
        const uint32_t so = (uint32_t)st * (KV_SZ * 2);
        const size_t ga = (size_t)(kt * 64 + row_a) * DH_ + c8;
        const size_t gb = (size_t)(kt * 64 + row_b) * DH_ + c8;
        cpa16(ksb + so + (row_a * LDH + c8) * 2, Kg + ga);
        cpa16(ksb + so + (row_b * LDH + c8) * 2, Kg + gb);
        cpa16(vsb + so + (row_a * LDH + c8) * 2, Vg + ga);
        cpa16(vsb + so + (row_b * LDH + c8) * 2, Vg + gb);
        cp_commit();
    };

    cpa16(qsb + (row_a * LDH + c8) * 2, Qg + (size_t)(q0 + row_a) * DH_ + c8);
    cpa16(qsb + (row_b * LDH + c8) * 2, Qg + (size_t)(q0 + row_b) * DH_ + c8);
    cpa16(ksb + (row_a * LDH + c8) * 2, Kg + (size_t)row_a * DH_ + c8);
    cpa16(ksb + (row_b * LDH + c8) * 2, Kg + (size_t)row_b * DH_ + c8);
    cpa16(vsb + (row_a * LDH + c8) * 2, Vg + (size_t)row_a * DH_ + c8);
    cpa16(vsb + (row_b * LDH + c8) * 2, Vg + (size_t)row_b * DH_ + c8);
    cp_commit();
    if (qt >= 1) prefetch(1, 1);

    float o[8][4];
#pragma unroll
    for (int ni = 0; ni < 8; ni++)
#pragma unroll
        for (int r = 0; r < 4; r++) o[ni][r] = 0.f;
    float osum[4] = { 0.f, 0.f, 0.f, 0.f };   // rowsums via ones-column MMA
    uint32_t qf[4][4];

    const uint32_t kaddr_l = (uint32_t)__cvta_generic_to_shared(
        &Kh[(wh * 32 + lrow) * LDH + lcol]);
    const uint32_t vaddr_l = (uint32_t)__cvta_generic_to_shared(
        &Vh[(wh * 32 + lrow) * LDH + lcol]);
    const uint32_t qaddr = qsb + ((wm * 16 + lrow) * LDH + lcol) * 2;

    auto body = [&](int kt, int st, bool diag) {
        const uint32_t kaddr0 = kaddr_l + (uint32_t)st * (KV_SZ * 2);
        const uint32_t kaddr1 = kaddr0 + 16 * LDH * 2;
        const uint32_t vaddr0 = vaddr_l + (uint32_t)st * (KV_SZ * 2);
        const uint32_t vaddr1 = vaddr0 + 16 * LDH * 2;

        float s[4][4];
#pragma unroll
        for (int j = 0; j < 4; j++)
#pragma unroll
            for (int r = 0; r < 4; r++) s[j][r] = 0.f;

#pragma unroll
        for (int ks = 0; ks < 4; ks++) {
            uint32_t r0[4], r1[4];
            ldmx4(r0, kaddr0 + ks * 32);
            ldmx4(r1, kaddr1 + ks * 32);
            uint32_t b0[2] = { r0[0], r0[2] };
            uint32_t b1[2] = { r0[1], r0[3] };
            uint32_t b2[2] = { r1[0], r1[2] };
            uint32_t b3[2] = { r1[1], r1[3] };
            MMA_F16(s[0], qf[ks], b0);
            MMA_F16(s[1], qf[ks], b1);
            MMA_F16(s[2], qf[ks], b2);
            MMA_F16(s[3], qf[ks], b3);
        }

        uint32_t pl[4], ph[4];
        if (!diag) {
#pragma unroll
            for (int j = 0; j < 4; j++) {
                uint32_t slo = h2u(__floats2half2_rn(s[j][0], s[j][1]));
                uint32_t shi = h2u(__floats2half2_rn(s[j][2], s[j][3]));
                asm("ex2.approx.f16x2 %0, %1;" : "=r"(pl[j]) : "r"(slo));
                asm("ex2.approx.f16x2 %0, %1;" : "=r"(ph[j]) : "r"(shi));
            }
        } else {
            const int row0 = q0 + wm * 16 + gr;
#pragma unroll
            for (int j = 0; j < 4; j++) {
                float p0 = exp2f(s[j][0]);
                float p1 = exp2f(s[j][1]);
                float p2 = exp2f(s[j][2]);
                float p3 = exp2f(s[j][3]);
                int colg = kt * 64 + wh * 32 + j * 8 + 2 * gc;
                if (colg     > row0)     p0 = 1.f;
                if (colg + 1 > row0)     p1 = 1.f;
                if (colg     > row0 + 8) p2 = 1.f;
                if (colg + 1 > row0 + 8) p3 = 1.f;
                pl[j] = h2u(__floats2half2_rn(p0, p1));
                ph[j] = h2u(__floats2half2_rn(p2, p3));
            }
        }

#pragma unroll
        for (int ks2 = 0; ks2 < 2; ks2++) {
            uint32_t a[4] = { pl[ks2 * 2], ph[ks2 * 2], pl[ks2 * 2 + 1], ph[ks2 * 2 + 1] };
            uint32_t vbase = (ks2 == 0) ? vaddr0 : vaddr1;
#pragma unroll
            for (int dg = 0; dg < 4; dg++) {
                uint32_t rv[4];
                ldmx4t(rv, vbase + dg * 32);
                uint32_t bA[2] = { rv[0], rv[1] };
                uint32_t bB[2] = { rv[2], rv[3] };
                MMA_F16(o[dg * 2],     a, bA);
                MMA_F16(o[dg * 2 + 1], a, bB);
            }
            uint32_t rv2[2];
            ldmx2t(rv2, vbase + (64 - lcol) * 2);
            uint32_t bO[2] = { rv2[0], rv2[1] };
            MMA_F16(osum, a, bO);
        }
    };

    int stg = 0;
    for (int kt = 0; kt < qt; kt++) {
        cp_wait<1>();
        __syncthreads();
        int st2 = stg + 2; if (st2 >= 3) st2 -= 3;
        if (kt + 2 <= qt) prefetch(kt + 2, st2);
        if (kt == 0) {
#pragma unroll
            for (int ks = 0; ks < 4; ks++)
                ldmx4(qf[ks], qaddr + ks * 32);
        }
        body(kt, stg, false);
        stg = (stg == 2) ? 0 : stg + 1;
    }

    cp_wait<0>();
    __syncthreads();
    if (qt == 0) {
#pragma unroll
        for (int ks = 0; ks < 4; ks++)
            ldmx4(qf[ks], qaddr + ks * 32);
    }
    body(qt, stg, true);

    __syncthreads();
    if (wh == 0) {
        if (gc == 0) {
            redS[wm * 16 + gr]     = osum[0];
            redS[wm * 16 + 8 + gr] = osum[2];
        }
#pragma unroll
        for (int ni = 0; ni < 8; ni++) {
            int c = ni * 8 + 2 * gc;
            *(float2*)&redO[(wm * 16 + gr) * 64 + c]     = make_float2(o[ni][0], o[ni][1]);
            *(float2*)&redO[(wm * 16 + 8 + gr) * 64 + c] = make_float2(o[ni][2], o[ni][3]);
        }
    }
    __syncthreads();

    if (wh == 1) {
        const int b = bh / H_;
        const int h = bh - b * H_;
        const float tailN = (float)(T_ - (qt + 1) * 64);
        const float* vt = g_TS + ((size_t)bh * 33 + (qt + 1)) * DH_;
#pragma unroll
        for (int half_ = 0; half_ < 2; half_++) {
            int rl = wm * 16 + gr + 8 * half_;
            int qi = q0 + rl;
            float own = (half_ == 0) ? osum[0] : osum[2];
            float denom = own + redS[rl] + tailN;
            float inv = 1.f / denom;
            half* dst = g_AOh + ((size_t)(b * T_ + qi)) * D_ + h * DH_;
#pragma unroll
            for (int ni = 0; ni < 8; ni++) {
                int c = ni * 8 + 2 * gc;
                float2 red = *(const float2*)&redO[rl * 64 + c];
                float2 vtv = *(const float2*)&vt[c];
                float v0 = (o[ni][half_ * 2 + 0] + red.x + vtv.x) * inv;
                float v1 = (o[ni][half_ * 2 + 1] + red.y + vtv.y) * inv;
                *(half2*)&dst[c] = __floats2half2_rn(v0, v1);
            }
        }
    }
}

// ---------------- launch -----------------
extern "C" void kernel_launch(void* const* d_in, const int* in_sizes, int n_in,
                              void* d_out, int out_size)
{
    const float* X  = (const float*)d_in[0];
    const float* Wq = (const float*)d_in[1];
    const float* bq = (const float*)d_in[2];
    const float* Wk = (const float*)d_in[3];
    const float* bk = (const float*)d_in[4];
    const float* Wv = (const float*)d_in[5];
    const float* bv = (const float*)d_in[6];
    const float* Wo = (const float*)d_in[7];
    const float* bo = (const float*)d_in[8];
    float* out = (float*)d_out;

    cudaFuncSetAttribute(attn_tc,    cudaFuncAttributeMaxDynamicSharedMemorySize, ATT_SMEM);
    cudaFuncSetAttribute(gemm_qkv_h, cudaFuncAttributeMaxDynamicSharedMemorySize, GEMM_SMEM);
    cudaFuncSetAttribute(gemm_out_h, cudaFuncAttributeMaxDynamicSharedMemorySize, GEMM_SMEM);

    const int total4 = XTOT4 + 4 * WTOT4;
    cvt_all<<<(total4 + 255) / 256, 256>>>(X, Wq, Wk, Wv, Wo);
    gemm_qkv_h<<<dim3(D_ / 128, M_ / 128, 3), 256, GEMM_SMEM>>>(bq, bk, bv);
    vtail<<<24, 1024>>>();
    attn_tc<<<dim3(T_ / 64, B_ * H_), 256, ATT_SMEM>>>();
    gemm_out_h<<<dim3(D_ / 128, M_ / 128), 256, GEMM_SMEM>>>(bo, out);
}

// round 17
// speedup vs baseline: 1.3696x; 1.0063x over previous
#include <cuda_runtime.h>
#include <cuda_fp16.h>
#include <cstdint>

#define B_   2
#define T_   2048
#define D_   768
#define H_   12
#define DH_  64
#define M_   (B_ * T_)   // 4096

// softmax scale folded into Q: 0.125 * log2(e)
#define QSCALE 0.18033688011112042f

// ---------------- scratch (static device globals; no allocation) ----------------
__device__ half  g_Xh [M_ * D_];             // X in fp16
__device__ half  g_Wqh[D_ * D_];
__device__ half  g_Wkh[D_ * D_];
__device__ half  g_Wvh[D_ * D_];
__device__ half  g_Woh[D_ * D_];
__device__ half  g_Qh [B_ * H_ * T_ * DH_];  // [B,H,T,Dh] fp16 (pre-scaled)
__device__ half  g_Kh [B_ * H_ * T_ * DH_];
__device__ half  g_Vh [B_ * H_ * T_ * DH_];
__device__ half  g_AOh[M_ * D_];             // attention out, [B,T, H*Dh] fp16
__device__ float g_TS [24 * 33 * DH_];       // per-(bh,tile) V tile-suffix sums

// ---------------- helpers ----------------
#define MMA_F16(c, a, b)                                                         \
    asm volatile(                                                                \
        "mma.sync.aligned.m16n8k16.row.col.f32.f16.f16.f32 "                     \
        "{%0,%1,%2,%3},{%4,%5,%6,%7},{%8,%9},{%0,%1,%2,%3};"                     \
        : "+f"((c)[0]), "+f"((c)[1]), "+f"((c)[2]), "+f"((c)[3])                 \
        : "r"((a)[0]), "r"((a)[1]), "r"((a)[2]), "r"((a)[3]),                    \
          "r"((b)[0]), "r"((b)[1]))

__device__ __forceinline__ void ldmx4(uint32_t* r, uint32_t addr) {
    asm volatile("ldmatrix.sync.aligned.m8n8.x4.shared.b16 {%0,%1,%2,%3}, [%4];"
                 : "=r"(r[0]), "=r"(r[1]), "=r"(r[2]), "=r"(r[3]) : "r"(addr));
}
__device__ __forceinline__ void ldmx4t(uint32_t* r, uint32_t addr) {
    asm volatile("ldmatrix.sync.aligned.m8n8.x4.trans.shared.b16 {%0,%1,%2,%3}, [%4];"
                 : "=r"(r[0]), "=r"(r[1]), "=r"(r[2]), "=r"(r[3]) : "r"(addr));
}
__device__ __forceinline__ void ldmx2t(uint32_t* r, uint32_t addr) {
    asm volatile("ldmatrix.sync.aligned.m8n8.x2.trans.shared.b16 {%0,%1}, [%2];"
                 : "=r"(r[0]), "=r"(r[1]) : "r"(addr));
}
__device__ __forceinline__ uint32_t h2u(half2 h) { return *reinterpret_cast<uint32_t*>(&h); }

__device__ __forceinline__ void cpa16(uint32_t saddr, const void* g) {
    asm volatile("cp.async.cg.shared.global [%0], [%1], 16;" :: "r"(saddr), "l"(g));
}
__device__ __forceinline__ void cp_commit() { asm volatile("cp.async.commit_group;"); }
template <int N>
__device__ __forceinline__ void cp_wait() { asm volatile("cp.async.wait_group %0;" :: "n"(N)); }

// ---------------- fp32 -> fp16 conversion of X and the 4 weight matrices --------
#define XTOT4 (M_ * D_ / 4)     // 786432
#define WTOT4 (D_ * D_ / 4)     // 147456

__global__ __launch_bounds__(256)
void cvt_all(const float* __restrict__ X,
             const float* __restrict__ Wq, const float* __restrict__ Wk,
             const float* __restrict__ Wv, const float* __restrict__ Wo)
{
    int i = blockIdx.x * 256 + threadIdx.x;
    const int total = XTOT4 + 4 * WTOT4;
    if (i >= total) return;
    const float* src; half* dst; int off;
    if (i < XTOT4) { src = X; dst = g_Xh; off = i; }
    else {
        int j = i - XTOT4;
        int w = j / WTOT4;
        off = j - w * WTOT4;
        src = (w == 0) ? Wq : (w == 1) ? Wk : (w == 2) ? Wv : Wo;
        dst = (w == 0) ? g_Wqh : (w == 1) ? g_Wkh : (w == 2) ? g_Wvh : g_Woh;
    }
    float4 v = ((const float4*)src)[off];
    uint2 u = make_uint2(h2u(__floats2half2_rn(v.x, v.y)),
                         h2u(__floats2half2_rn(v.z, v.w)));
    ((uint2*)dst)[off] = u;
}

// ---------------- fp16 GEMM mainloop, 128x128 tile, 3-stage cp.async ring -------
// 8 warps = 4(m) x 2(n); warp tile 32(m) x 64(n); k-chunk 64; ONE barrier/iter.
#define LDA 72                        // A stage row stride (halves)
#define LDW 136                       // W stage row stride (halves): 272B = 4-bank stagger
#define GA_SZ (128 * LDA)             // halves per A stage
#define GW_SZ (64 * LDW)              // halves per W stage
#define GEMM_SMEM ((3 * GA_SZ + 3 * GW_SZ) * 2)   // 107520 B

__device__ __forceinline__
void gemm_h_mainloop(const half* __restrict__ A, const half* __restrict__ W,
                     float c[2][8][4], half* As, half* Ws)
{
    const int tid  = threadIdx.x;
    const int lane = tid & 31;
    const int wid  = tid >> 5;
    const int wm   = wid & 3;
    const int wn   = wid >> 2;
    const int m0   = blockIdx.y * 128;
    const int n0   = blockIdx.x * 128;
    const int lrow = lane & 15;
    const int lcol = (lane >> 4) * 8;

#pragma unroll
    for (int mi = 0; mi < 2; mi++)
#pragma unroll
        for (int j = 0; j < 8; j++)
#pragma unroll
            for (int r = 0; r < 4; r++) c[mi][j][r] = 0.f;

    const uint32_t asb = (uint32_t)__cvta_generic_to_shared(As);
    const uint32_t wsb = (uint32_t)__cvta_generic_to_shared(Ws);

    // per-thread load coordinates
    const int arow[4] = { (tid + 0) >> 3, (tid + 256) >> 3, (tid + 512) >> 3, (tid + 768) >> 3 };
    const int ac8     = (tid & 7) * 8;
    const int wrow[4] = { (tid + 0) >> 4, (tid + 256) >> 4, (tid + 512) >> 4, (tid + 768) >> 4 };
    const int wc8     = (tid & 15) * 8;

    auto prefetch = [&](int it, int st) {
        const int kk = it * 64;
        const uint32_t ao = (uint32_t)st * (GA_SZ * 2);
        const uint32_t wo = (uint32_t)st * (GW_SZ * 2);
#pragma unroll
        for (int r = 0; r < 4; r++)
            cpa16(asb + ao + (arow[r] * LDA + ac8) * 2,
                  A + (size_t)(m0 + arow[r]) * D_ + kk + ac8);
#pragma unroll
        for (int r = 0; r < 4; r++)
            cpa16(wsb + wo + (wrow[r] * LDW + wc8) * 2,
                  W + (size_t)(kk + wrow[r]) * D_ + n0 + wc8);
        cp_commit();
    };

    const int NIT = D_ / 64;   // 12
    prefetch(0, 0);
    prefetch(1, 1);

    const uint32_t aaddr_l = (uint32_t)__cvta_generic_to_shared(
        &As[(wm * 32 + lrow) * LDA + lcol]);
    const uint32_t baddr_l = (uint32_t)__cvta_generic_to_shared(
        &Ws[lrow * LDW + wn * 64 + lcol]);

    int stg = 0;
    for (int it = 0; it < NIT; it++) {
        if (it == NIT - 1) { cp_wait<0>(); } else { cp_wait<1>(); }
        __syncthreads();                       // stage consumed at it-1 now free
        int st2 = stg + 2; if (st2 >= 3) st2 -= 3;
        if (it + 2 < NIT) prefetch(it + 2, st2);

        const uint32_t aaddr0 = aaddr_l + (uint32_t)stg * (GA_SZ * 2);
        const uint32_t aaddr1 = aaddr0 + 16 * LDA * 2;
        const uint32_t baddr  = baddr_l + (uint32_t)stg * (GW_SZ * 2);

#pragma unroll
        for (int ks = 0; ks < 4; ks++) {
            uint32_t af[2][4];
            ldmx4(af[0], aaddr0 + ks * 32);
            ldmx4(af[1], aaddr1 + ks * 32);
#pragma unroll
            for (int ni = 0; ni < 4; ni++) {
                uint32_t bf[4];
                ldmx4t(bf, baddr + (ks * 16 * LDW + ni * 16) * 2);
                uint32_t b0[2] = { bf[0], bf[1] };
                uint32_t b1[2] = { bf[2], bf[3] };
                MMA_F16(c[0][ni * 2],     af[0], b0);
                MMA_F16(c[0][ni * 2 + 1], af[0], b1);
                MMA_F16(c[1][ni * 2],     af[1], b0);
                MMA_F16(c[1][ni * 2 + 1], af[1], b1);
            }
        }
        stg = (stg == 2) ? 0 : stg + 1;
    }
    __syncthreads();    // epilogue may reuse nothing, but keep warps aligned
}

// QKV projection: blockIdx.z selects matrix; epilogue scatters half into [B,H,T,Dh].
// Q is pre-scaled by QSCALE so attention can use exp2 directly.
__global__ __launch_bounds__(256, 2)
void gemm_qkv_h(const float* __restrict__ bq, const float* __restrict__ bk,
                const float* __restrict__ bv)
{
    extern __shared__ __align__(16) half gsm[];
    half* As = gsm;
    half* Ws = gsm + 3 * GA_SZ;

    const int z = blockIdx.z;
    const half*  W  = (z == 0) ? g_Wqh : (z == 1) ? g_Wkh : g_Wvh;
    const float* bb = (z == 0) ? bq    : (z == 1) ? bk    : bv;
    half*        Cd = (z == 0) ? g_Qh  : (z == 1) ? g_Kh  : g_Vh;
    const float  sc = (z == 0) ? QSCALE : 1.f;

    float c[2][8][4];
    gemm_h_mainloop(g_Xh, W, c, As, Ws);

    const int lane = threadIdx.x & 31;
    const int wid  = threadIdx.x >> 5;
    const int wm   = wid & 3;
    const int wn   = wid >> 2;
    const int gr   = lane >> 2;
    const int gc   = lane & 3;
    const int m0   = blockIdx.y * 128;
    const int n0   = blockIdx.x * 128;

#pragma unroll
    for (int mi = 0; mi < 2; mi++) {
#pragma unroll
        for (int j = 0; j < 8; j++) {
            int col = n0 + wn * 64 + j * 8 + 2 * gc;
            float b0 = bb[col], b1 = bb[col + 1];
            int h  = col >> 6;
            int dh = col & 63;
#pragma unroll
            for (int hp = 0; hp < 2; hp++) {
                int row = m0 + wm * 32 + mi * 16 + gr + hp * 8;
                int bt  = row >> 11;
                int t   = row & (T_ - 1);
                half2 v = __floats2half2_rn((c[mi][j][hp * 2] + b0) * sc,
                                            (c[mi][j][hp * 2 + 1] + b1) * sc);
                *(half2*)&Cd[((size_t)(bt * H_ + h) * T_ + t) * DH_ + dh] = v;
            }
        }
    }
}

// Output projection: AO(half) @ Wo + bo -> fp32 out.
__global__ __launch_bounds__(256, 2)
void gemm_out_h(const float* __restrict__ bo, float* __restrict__ out)
{
    extern __shared__ __align__(16) half gsm[];
    half* As = gsm;
    half* Ws = gsm + 3 * GA_SZ;

    float c[2][8][4];
    gemm_h_mainloop(g_AOh, g_Woh, c, As, Ws);

    const int lane = threadIdx.x & 31;
    const int wid  = threadIdx.x >> 5;
    const int wm   = wid & 3;
    const int wn   = wid >> 2;
    const int gr   = lane >> 2;
    const int gc   = lane & 3;
    const int m0   = blockIdx.y * 128;
    const int n0   = blockIdx.x * 128;

#pragma unroll
    for (int mi = 0; mi < 2; mi++) {
#pragma unroll
        for (int j = 0; j < 8; j++) {
            int col = n0 + wn * 64 + j * 8 + 2 * gc;
            float b0 = bo[col], b1 = bo[col + 1];
#pragma unroll
            for (int hp = 0; hp < 2; hp++) {
                int row = m0 + wm * 32 + mi * 16 + gr + hp * 8;
                *(float2*)&out[(size_t)row * D_ + col] =
                    make_float2(c[mi][j][hp * 2] + b0, c[mi][j][hp * 2 + 1] + b1);
            }
        }
    }
}

// ---------------- fused V tile totals + suffix scan ----------------
__global__ __launch_bounds__(1024)
void vtail()
{
    __shared__ float ctot[32][64];
    __shared__ float suf[33][64];
    const int bh  = blockIdx.x;
    const int tid = threadIdx.x;
    const int d   = tid & 63;
    const int y   = tid >> 6;              // 0..15
    const half* V = g_Vh + (size_t)bh * T_ * DH_ + d;

#pragma unroll
    for (int rep = 0; rep < 2; rep++) {
        const int tl = y + rep * 16;
        const half* Vp = V + (size_t)tl * 64 * DH_;
        float sum = 0.f;
#pragma unroll 16
        for (int t = 0; t < 64; t++)
            sum += __half2float(Vp[(size_t)t * DH_]);
        ctot[tl][d] = sum;
    }
    __syncthreads();

    if (y == 0) {
        float s = 0.f;
        suf[32][d] = 0.f;
#pragma unroll
        for (int t = 31; t >= 0; t--) {
            s += ctot[t][d];
            suf[t][d] = s;
        }
    }
    __syncthreads();

    float* TS = g_TS + (size_t)bh * 33 * DH_;
#pragma unroll
    for (int i = tid; i < 33 * 64; i += 1024)
        TS[i] = suf[i >> 6][i & 63];
}

// ---------------- fp16 tensor-core causal attention (zero-fill semantics) -------
// [round-16 best version — unchanged]
#define LDH 72
#define KV_SZ (64 * LDH)                        // halves per K or V stage
#define ATT_SMEM ((64 * LDH + 6 * KV_SZ) * 2 + 4 * 16 * 64 * 4 + 64 * 4)  // 81152 B

__global__ __launch_bounds__(256, 2)
void attn_tc()
{
    extern __shared__ __align__(16) uint8_t smraw[];
    half* Qh = (half*)smraw;                  // 64 x LDH
    half* Kh = Qh + 64 * LDH;                 // 3 stages
    half* Vh = Kh + 3 * KV_SZ;                // 3 stages
    float* redO = (float*)(Vh + 3 * KV_SZ);   // 4*16 x 64
    float* redS = redO + 4 * 16 * 64;

    const int tid  = threadIdx.x;
    const int lane = tid & 31;
    const int wid  = tid >> 5;
    const int wm   = wid & 3;
    const int wh   = wid >> 2;
    const int gr   = lane >> 2;
    const int gc   = lane & 3;
    const int lrow = lane & 15;
    const int lcol = (lane >> 4) * 8;

    const int bh = blockIdx.y;
    const int qt = gridDim.x - 1 - blockIdx.x;    // heavy tiles first
    const int q0 = qt * 64;

    const half* Qg = g_Qh + (size_t)bh * T_ * DH_;
    const half* Kg = g_Kh + (size_t)bh * T_ * DH_;
    const half* Vg = g_Vh + (size_t)bh * T_ * DH_;

    const uint32_t qsb = (uint32_t)__cvta_generic_to_shared(Qh);
    const uint32_t ksb = (uint32_t)__cvta_generic_to_shared(Kh);
    const uint32_t vsb = (uint32_t)__cvta_generic_to_shared(Vh);

    const int c8    = (tid & 7) * 8;
    const int row_a = (tid + 0)   >> 3;
    const int row_b = (tid + 256) >> 3;

    // preset ones-column (V cols 64-71) in all 3 stages; cp.async never touches it
    if (tid < 192) {
        int st  = tid >> 6;
        int row = tid & 63;
        uint4 ones;
        ones.x = ones.y = ones.z = ones.w = 0x3C003C00u;   // half 1.0 x8
        *(uint4*)&Vh[st * KV_SZ + row * LDH + 64] = ones;
    }

    auto prefetch = [&](int kt, int st) {
        const uint32_t so = (uint32_t)st * (KV_SZ * 2);
        const size_t ga = (size_t)(kt * 64 + row_a) * DH_ + c8;
        const size_t gb = (size_t)(kt * 64 + row_b) * DH_ + c8;
        cpa16(ksb + so + (row_a * LDH + c8) * 2, Kg + ga);
        cpa16(ksb + so + (row_b * LDH + c8) * 2, Kg + gb);
        cpa16(vsb + so + (row_a * LDH + c8) * 2, Vg + ga);
        cpa16(vsb + so + (row_b * LDH + c8) * 2, Vg + gb);
        cp_commit();
    };

    cpa16(qsb + (row_a * LDH + c8) * 2, Qg + (size_t)(q0 + row_a) * DH_ + c8);
    cpa16(qsb + (row_b * LDH + c8) * 2, Qg + (size_t)(q0 + row_b) * DH_ + c8);
    cpa16(ksb + (row_a * LDH + c8) * 2, Kg + (size_t)row_a * DH_ + c8);
    cpa16(ksb + (row_b * LDH + c8) * 2, Kg + (size_t)row_b * DH_ + c8);
    cpa16(vsb + (row_a * LDH + c8) * 2, Vg + (size_t)row_a * DH_ + c8);
    cpa16(vsb + (row_b * LDH + c8) * 2, Vg + (size_t)row_b * DH_ + c8);
    cp_commit();
    if (qt >= 1) prefetch(1, 1);

    float o[8][4];
#pragma unroll
    for (int ni = 0; ni < 8; ni++)
#pragma unroll
        for (int r = 0; r < 4; r++) o[ni][r] = 0.f;
    float osum[4] = { 0.f, 0.f, 0.f, 0.f };   // rowsums via ones-column MMA
    uint32_t qf[4][4];

    const uint32_t kaddr_l = (uint32_t)__cvta_generic_to_shared(
        &Kh[(wh * 32 + lrow) * LDH + lcol]);
    const uint32_t vaddr_l = (uint32_t)__cvta_generic_to_shared(
        &Vh[(wh * 32 + lrow) * LDH + lcol]);
    const uint32_t qaddr = qsb + ((wm * 16 + lrow) * LDH + lcol) * 2;

    auto body = [&](int kt, int st, bool diag) {
        const uint32_t kaddr0 = kaddr_l + (uint32_t)st * (KV_SZ * 2);
        const uint32_t kaddr1 = kaddr0 + 16 * LDH * 2;
        const uint32_t vaddr0 = vaddr_l + (uint32_t)st * (KV_SZ * 2);
        const uint32_t vaddr1 = vaddr0 + 16 * LDH * 2;

        float s[4][4];
#pragma unroll
        for (int j = 0; j < 4; j++)
#pragma unroll
            for (int r = 0; r < 4; r++) s[j][r] = 0.f;

#pragma unroll
        for (int ks = 0; ks < 4; ks++) {
            uint32_t r0[4], r1[4];
            ldmx4(r0, kaddr0 + ks * 32);
            ldmx4(r1, kaddr1 + ks * 32);
            uint32_t b0[2] = { r0[0], r0[2] };
            uint32_t b1[2] = { r0[1], r0[3] };
            uint32_t b2[2] = { r1[0], r1[2] };
            uint32_t b3[2] = { r1[1], r1[3] };
            MMA_F16(s[0], qf[ks], b0);
            MMA_F16(s[1], qf[ks], b1);
            MMA_F16(s[2], qf[ks], b2);
            MMA_F16(s[3], qf[ks], b3);
        }

        uint32_t pl[4], ph[4];
        if (!diag) {
#pragma unroll
            for (int j = 0; j < 4; j++) {
                uint32_t slo = h2u(__floats2half2_rn(s[j][0], s[j][1]));
                uint32_t shi = h2u(__floats2half2_rn(s[j][2], s[j][3]));
                asm("ex2.approx.f16x2 %0, %1;" : "=r"(pl[j]) : "r"(slo));
                asm("ex2.approx.f16x2 %0, %1;" : "=r"(ph[j]) : "r"(shi));
            }
        } else {
            const int row0 = q0 + wm * 16 + gr;
#pragma unroll
            for (int j = 0; j < 4; j++) {
                float p0 = exp2f(s[j][0]);
                float p1 = exp2f(s[j][1]);
                float p2 = exp2f(s[j][2]);
                float p3 = exp2f(s[j][3]);
                int colg = kt * 64 + wh * 32 + j * 8 + 2 * gc;
                if (colg     > row0)     p0 = 1.f;
                if (colg + 1 > row0)     p1 = 1.f;
                if (colg     > row0 + 8) p2 = 1.f;
                if (colg + 1 > row0 + 8) p3 = 1.f;
                pl[j] = h2u(__floats2half2_rn(p0, p1));
                ph[j] = h2u(__floats2half2_rn(p2, p3));
            }
        }

#pragma unroll
        for (int ks2 = 0; ks2 < 2; ks2++) {
            uint32_t a[4] = { pl[ks2 * 2], ph[ks2 * 2], pl[ks2 * 2 + 1], ph[ks2 * 2 + 1] };
            uint32_t vbase = (ks2 == 0) ? vaddr0 : vaddr1;
#pragma unroll
            for (int dg = 0; dg < 4; dg++) {
                uint32_t rv[4];
                ldmx4t(rv, vbase + dg * 32);
                uint32_t bA[2] = { rv[0], rv[1] };
                uint32_t bB[2] = { rv[2], rv[3] };
                MMA_F16(o[dg * 2],     a, bA);
                MMA_F16(o[dg * 2 + 1], a, bB);
            }
            uint32_t rv2[2];
            ldmx2t(rv2, vbase + (64 - lcol) * 2);
            uint32_t bO[2] = { rv2[0], rv2[1] };
            MMA_F16(osum, a, bO);
        }
    };

    int stg = 0;
    for (int kt = 0; kt < qt; kt++) {
        cp_wait<1>();
        __syncthreads();
        int st2 = stg + 2; if (st2 >= 3) st2 -= 3;
        if (kt + 2 <= qt) prefetch(kt + 2, st2);
        if (kt == 0) {
#pragma unroll
            for (int ks = 0; ks < 4; ks++)
                ldmx4(qf[ks], qaddr + ks * 32);
        }
        body(kt, stg, false);
        stg = (stg == 2) ? 0 : stg + 1;
    }

    cp_wait<0>();
    __syncthreads();
    if (qt == 0) {
#pragma unroll
        for (int ks = 0; ks < 4; ks++)
            ldmx4(qf[ks], qaddr + ks * 32);
    }
    body(qt, stg, true);

    __syncthreads();
    if (wh == 0) {
        if (gc == 0) {
            redS[wm * 16 + gr]     = osum[0];
            redS[wm * 16 + 8 + gr] = osum[2];
        }
#pragma unroll
        for (int ni = 0; ni < 8; ni++) {
            int c = ni * 8 + 2 * gc;
            *(float2*)&redO[(wm * 16 + gr) * 64 + c]     = make_float2(o[ni][0], o[ni][1]);
            *(float2*)&redO[(wm * 16 + 8 + gr) * 64 + c] = make_float2(o[ni][2], o[ni][3]);
        }
    }
    __syncthreads();

    if (wh == 1) {
        const int b = bh / H_;
        const int h = bh - b * H_;
        const float tailN = (float)(T_ - (qt + 1) * 64);
        const float* vt = g_TS + ((size_t)bh * 33 + (qt + 1)) * DH_;
#pragma unroll
        for (int half_ = 0; half_ < 2; half_++) {
            int rl = wm * 16 + gr + 8 * half_;
            int qi = q0 + rl;
            float own = (half_ == 0) ? osum[0] : osum[2];
            float denom = own + redS[rl] + tailN;
            float inv = 1.f / denom;
            half* dst = g_AOh + ((size_t)(b * T_ + qi)) * D_ + h * DH_;
#pragma unroll
            for (int ni = 0; ni < 8; ni++) {
                int c = ni * 8 + 2 * gc;
                float2 red = *(const float2*)&redO[rl * 64 + c];
                float2 vtv = *(const float2*)&vt[c];
                float v0 = (o[ni][half_ * 2 + 0] + red.x + vtv.x) * inv;
                float v1 = (o[ni][half_ * 2 + 1] + red.y + vtv.y) * inv;
                *(half2*)&dst[c] = __floats2half2_rn(v0, v1);
            }
        }
    }
}

// ---------------- launch -----------------
extern "C" void kernel_launch(void* const* d_in, const int* in_sizes, int n_in,
                              void* d_out, int out_size)
{
    const float* X  = (const float*)d_in[0];
    const float* Wq = (const float*)d_in[1];
    const float* bq = (const float*)d_in[2];
    const float* Wk = (const float*)d_in[3];
    const float* bk = (const float*)d_in[4];
    const float* Wv = (const float*)d_in[5];
    const float* bv = (const float*)d_in[6];
    const float* Wo = (const float*)d_in[7];
    const float* bo = (const float*)d_in[8];
    float* out = (float*)d_out;

    cudaFuncSetAttribute(attn_tc,    cudaFuncAttributeMaxDynamicSharedMemorySize, ATT_SMEM);
    cudaFuncSetAttribute(gemm_qkv_h, cudaFuncAttributeMaxDynamicSharedMemorySize, GEMM_SMEM);
    cudaFuncSetAttribute(gemm_out_h, cudaFuncAttributeMaxDynamicSharedMemorySize, GEMM_SMEM);

    const int total4 = XTOT4 + 4 * WTOT4;
    cvt_all<<<(total4 + 255) / 256, 256>>>(X, Wq, Wk, Wv, Wo);
    gemm_qkv_h<<<dim3(D_ / 128, M_ / 128, 3), 256, GEMM_SMEM>>>(bq, bk, bv);
    vtail<<<24, 1024>>>();
    attn_tc<<<dim3(T_ / 64, B_ * H_), 256, ATT_SMEM>>>();
    gemm_out_h<<<dim3(D_ / 128, M_ / 128), 256, GEMM_SMEM>>>(bo, out);
}